// round 5
// baseline (speedup 1.0000x reference)
#include <cuda_runtime.h>
#include <float.h>

#define S_    1600
#define DIM_  384
#define NH_   6
#define DH_   64
#define INNER_ 384
#define HID_  1536
#define NL_   6
#define GW_   40
#define TOPK_ 32
#define SCALE_ 0.05103103630798288f   // 384^-0.5

// ---------------- device scratch ----------------
__device__ float g_h[S_*DIM_];
__device__ float g_n[S_*DIM_];
__device__ float g_q[NH_*S_*DH_];
__device__ float g_k[NH_*S_*DH_];
__device__ float g_v[NH_*S_*DH_];
__device__ float g_pb[NH_*S_*64];
__device__ float g_rbT[64*64];
__device__ unsigned g_skey[(long long)NH_*S_*S_];   // monotone-uint score keys
__device__ float g_att[S_*INNER_];
__device__ float g_ff1[S_*HID_];

// ---------------- trivial kernels ----------------
__global__ void init_h_kernel(const float* __restrict__ x) {
    int i = blockIdx.x * blockDim.x + threadIdx.x;
    if (i < S_*DIM_) g_h[i] = x[i];
}
__global__ void write_out_kernel(float* __restrict__ out) {
    int i = blockIdx.x * blockDim.x + threadIdx.x;
    if (i < S_*DIM_) out[i] = g_h[i];
}
__global__ void rbT_kernel(const float* __restrict__ rb) {
    int i = blockIdx.x * blockDim.x + threadIdx.x;
    if (i < 64*64) {
        int d = i >> 6, m = i & 63;
        g_rbT[d*64 + m] = (m < 49) ? rb[m*64 + d] : 0.f;
    }
}

// ---------------- LayerNorm ----------------
__global__ void ln_kernel(const float* __restrict__ gamma, const float* __restrict__ beta) {
    int row = blockIdx.x;
    const float* x = g_h + row * DIM_;
    float s = 0.f, s2 = 0.f;
    for (int i = threadIdx.x; i < DIM_; i += blockDim.x) { float v = x[i]; s += v; s2 += v*v; }
    for (int o = 16; o; o >>= 1) {
        s  += __shfl_xor_sync(0xffffffffu, s,  o);
        s2 += __shfl_xor_sync(0xffffffffu, s2, o);
    }
    __shared__ float rs[4], rs2[4];
    int w = threadIdx.x >> 5;
    if ((threadIdx.x & 31) == 0) { rs[w] = s; rs2[w] = s2; }
    __syncthreads();
    s  = rs[0]  + rs[1]  + rs[2]  + rs[3];
    s2 = rs2[0] + rs2[1] + rs2[2] + rs2[3];
    float mean = s * (1.f / DIM_);
    float var  = s2 * (1.f / DIM_) - mean * mean;
    float inv  = rsqrtf(var + 1e-5f);
    for (int i = threadIdx.x; i < DIM_; i += blockDim.x)
        g_n[row*DIM_ + i] = (x[i] - mean) * inv * gamma[i] + beta[i];
}

// ========== 128x128x16 SGEMM, 8x8 register tiles ==========
#define LDP 132
template<int MODE>
__global__ void __launch_bounds__(256) gemm128(const float* __restrict__ Bp,
                                               const float* __restrict__ bias,
                                               int N, int K) {
    const float* A = (MODE == 0 || MODE == 2) ? g_n : (MODE == 1 ? g_att : g_ff1);
    const float* B = Bp;
    __shared__ __align__(16) float As[16][LDP];
    __shared__ __align__(16) float Bs[16][LDP];
    int tid = threadIdx.x;
    int tx = tid & 15, ty = tid >> 4;
    int m0 = blockIdx.y * 128, n0 = blockIdx.x * 128;
    int ar = tid >> 2, ac = (tid & 3) * 4;
    int bkr = tid >> 4, bc = (tid & 15) * 4;
    float acc[2][2][4][4] = {};
    for (int k0 = 0; k0 < K; k0 += 16) {
#pragma unroll
        for (int p = 0; p < 2; p++) {
            int m = m0 + ar + p*64;
            float4 av = (m < S_) ? *reinterpret_cast<const float4*>(A + (size_t)m * K + k0 + ac)
                                 : make_float4(0.f,0.f,0.f,0.f);
            As[ac+0][ar + p*64] = av.x; As[ac+1][ar + p*64] = av.y;
            As[ac+2][ar + p*64] = av.z; As[ac+3][ar + p*64] = av.w;
            float4 bv = *reinterpret_cast<const float4*>(B + (size_t)(k0 + bkr) * N + n0 + bc + p*64);
            *reinterpret_cast<float4*>(&Bs[bkr][bc + p*64]) = bv;
        }
        __syncthreads();
#pragma unroll
        for (int kk = 0; kk < 16; kk++) {
            float av[2][4], bv[2][4];
#pragma unroll
            for (int p = 0; p < 2; p++) {
                float4 a4 = *reinterpret_cast<const float4*>(&As[kk][ty*4 + p*64]);
                float4 b4 = *reinterpret_cast<const float4*>(&Bs[kk][tx*4 + p*64]);
                av[p][0]=a4.x; av[p][1]=a4.y; av[p][2]=a4.z; av[p][3]=a4.w;
                bv[p][0]=b4.x; bv[p][1]=b4.y; bv[p][2]=b4.z; bv[p][3]=b4.w;
            }
#pragma unroll
            for (int qi = 0; qi < 2; qi++)
#pragma unroll
            for (int qj = 0; qj < 2; qj++)
#pragma unroll
            for (int i = 0; i < 4; i++)
#pragma unroll
            for (int j = 0; j < 4; j++)
                acc[qi][qj][i][j] = fmaf(av[qi][i], bv[qj][j], acc[qi][qj][i][j]);
        }
        __syncthreads();
    }
#pragma unroll
    for (int qi = 0; qi < 2; qi++)
#pragma unroll
    for (int i = 0; i < 4; i++) {
        int m = m0 + qi*64 + ty*4 + i;
        if (m >= S_) continue;
#pragma unroll
        for (int qj = 0; qj < 2; qj++)
#pragma unroll
        for (int j = 0; j < 4; j++) {
            int n = n0 + qj*64 + tx*4 + j;
            float v = acc[qi][qj][i][j];
            if (MODE == 0) {
                int idx = n / 3, r = n - idx * 3;
                int hh = idx >> 6, d = idx & 63;
                float* dst = (r == 0) ? g_q : (r == 1) ? g_k : g_v;
                dst[(hh * S_ + m) * DH_ + d] = v;
            } else if (MODE == 1) {
                g_h[m * DIM_ + n] += v;
            } else if (MODE == 2) {
                float t = v + bias[n];
                g_ff1[m * HID_ + n] = t > 0.f ? t : 0.2f * t;
            } else {
                g_h[m * DIM_ + n] += v + bias[n];
            }
        }
    }
}

// ---------------- pb GEMM: g_pb[9600x64] = g_q @ g_rbT ----------------
__global__ void __launch_bounds__(256) pb_gemm() {
    const float* A = g_q;
    const float* B = g_rbT;
    __shared__ __align__(16) float As[16][68];
    __shared__ __align__(16) float Bs[16][68];
    int tid = threadIdx.x;
    int tx = tid & 15, ty = tid >> 4;
    int m0 = blockIdx.y * 64;
    int arow = tid >> 2, acol = (tid & 3) * 4;
    int brow = tid >> 4, bcol = (tid & 15) * 4;
    float acc[4][4] = {};
    for (int k0 = 0; k0 < 64; k0 += 16) {
        float4 av = *reinterpret_cast<const float4*>(A + (size_t)(m0 + arow) * 64 + k0 + acol);
        As[acol+0][arow] = av.x; As[acol+1][arow] = av.y;
        As[acol+2][arow] = av.z; As[acol+3][arow] = av.w;
        float4 bv = *reinterpret_cast<const float4*>(B + (size_t)(k0 + brow) * 64 + bcol);
        *reinterpret_cast<float4*>(&Bs[brow][bcol]) = bv;
        __syncthreads();
#pragma unroll
        for (int kk = 0; kk < 16; kk++) {
            float4 a4 = *reinterpret_cast<const float4*>(&As[kk][ty*4]);
            float4 b4 = *reinterpret_cast<const float4*>(&Bs[kk][tx*4]);
            float ar[4] = {a4.x, a4.y, a4.z, a4.w};
            float br[4] = {b4.x, b4.y, b4.z, b4.w};
#pragma unroll
            for (int i = 0; i < 4; i++)
#pragma unroll
                for (int j = 0; j < 4; j++)
                    acc[i][j] = fmaf(ar[i], br[j], acc[i][j]);
        }
        __syncthreads();
    }
#pragma unroll
    for (int i = 0; i < 4; i++)
#pragma unroll
        for (int j = 0; j < 4; j++)
            g_pb[(m0 + ty*4 + i) * 64 + tx*4 + j] = acc[i][j];
}

// ---------------- scores -> monotone uint keys ----------------
__global__ void __launch_bounds__(256) scores128() {
    int h = blockIdx.z;
    const float* Q  = g_q + (size_t)h * S_ * DH_;
    const float* Km = g_k + (size_t)h * S_ * DH_;
    __shared__ __align__(16) float Qs[16][LDP];
    __shared__ __align__(16) float Ks[16][LDP];
    int tid = threadIdx.x;
    int tx = tid & 15, ty = tid >> 4;
    int m0 = blockIdx.y * 128, n0 = blockIdx.x * 128;
    int ar = tid >> 2, ac = (tid & 3) * 4;
    float acc[2][2][4][4] = {};
    for (int k0 = 0; k0 < DH_; k0 += 16) {
#pragma unroll
        for (int p = 0; p < 2; p++) {
            int m = m0 + ar + p*64;
            float4 qv = (m < S_) ? *reinterpret_cast<const float4*>(Q + (size_t)m * DH_ + k0 + ac)
                                 : make_float4(0.f,0.f,0.f,0.f);
            Qs[ac+0][ar + p*64] = qv.x; Qs[ac+1][ar + p*64] = qv.y;
            Qs[ac+2][ar + p*64] = qv.z; Qs[ac+3][ar + p*64] = qv.w;
            int n = n0 + ar + p*64;
            float4 kv = (n < S_) ? *reinterpret_cast<const float4*>(Km + (size_t)n * DH_ + k0 + ac)
                                 : make_float4(0.f,0.f,0.f,0.f);
            Ks[ac+0][ar + p*64] = kv.x; Ks[ac+1][ar + p*64] = kv.y;
            Ks[ac+2][ar + p*64] = kv.z; Ks[ac+3][ar + p*64] = kv.w;
        }
        __syncthreads();
#pragma unroll
        for (int kk = 0; kk < 16; kk++) {
            float av[2][4], bv[2][4];
#pragma unroll
            for (int p = 0; p < 2; p++) {
                float4 a4 = *reinterpret_cast<const float4*>(&Qs[kk][ty*4 + p*64]);
                float4 b4 = *reinterpret_cast<const float4*>(&Ks[kk][tx*4 + p*64]);
                av[p][0]=a4.x; av[p][1]=a4.y; av[p][2]=a4.z; av[p][3]=a4.w;
                bv[p][0]=b4.x; bv[p][1]=b4.y; bv[p][2]=b4.z; bv[p][3]=b4.w;
            }
#pragma unroll
            for (int qi = 0; qi < 2; qi++)
#pragma unroll
            for (int qj = 0; qj < 2; qj++)
#pragma unroll
            for (int i = 0; i < 4; i++)
#pragma unroll
            for (int j = 0; j < 4; j++)
                acc[qi][qj][i][j] = fmaf(av[qi][i], bv[qj][j], acc[qi][qj][i][j]);
        }
        __syncthreads();
    }
#pragma unroll
    for (int qi = 0; qi < 2; qi++)
#pragma unroll
    for (int i = 0; i < 4; i++) {
        int q = m0 + qi*64 + ty*4 + i;
        if (q >= S_) continue;
        int qv = q / GW_, qh = q - qv * GW_;
        const float* pbq = g_pb + ((size_t)h * S_ + q) * 64;
        float pb0 = pbq[0];
        unsigned* srow = g_skey + ((size_t)h * S_ + q) * S_;
#pragma unroll
        for (int qj = 0; qj < 2; qj++)
#pragma unroll
        for (int j = 0; j < 4; j++) {
            int kq = n0 + qj*64 + tx*4 + j;
            if (kq >= S_) continue;
            int kv = kq / GW_, kh = kq - kv * GW_;
            int dv = kv - qv, dh = kh - qh;
            int ad = (dv < 0 ? -dv : dv) + (dh < 0 ? -dh : dh);
            float pbv = (ad <= 3) ? pbq[(dv + 3) * 7 + (dh + 3)] : pb0;
            float s = (acc[qi][qj][i][j] + pbv) * SCALE_;
            unsigned b = __float_as_uint(s);
            srow[kq] = (b & 0x80000000u) ? ~b : (b | 0x80000000u);
        }
    }
}

// ---------------- per-row: radix select (compacting, race-fixed) + softmax + sparse P.V ----------------
__global__ void __launch_bounds__(256) attn_row_kernel() {
    int bx = blockIdx.x;                 // h*S + q
    int h = bx / S_, q = bx - h * S_;
    const unsigned* srow = g_skey + (size_t)bx * S_;
    __shared__ unsigned su[S_];
    __shared__ unsigned hist[256];
    __shared__ unsigned short cand[S_];
    __shared__ unsigned short cand2[S_];
    __shared__ int   sidx[256];
    __shared__ float sval[256];
    __shared__ float pvred[4][DH_];
    __shared__ unsigned smaxw[8];
    __shared__ float ssum[8];
    __shared__ int sh_b, sh_k, sh_cnt, sh_cc;
    __shared__ float sh_inv;
    __shared__ unsigned sh_maxu;
    int tid = threadIdx.x, nt = blockDim.x;
    int wid = tid >> 5, lane = tid & 31;

    // load keys + hist pass (shift 24) + max key
    if (tid < 256) hist[tid] = 0u;
    if (tid == 0) { sh_k = TOPK_; sh_cnt = 0; sh_cc = 0; }
    __syncthreads();
    unsigned mxu = 0u;
    const uint4* srow4 = reinterpret_cast<const uint4*>(srow);
    for (int i = tid; i < S_/4; i += nt) {
        uint4 u4 = srow4[i];
        unsigned uu[4] = {u4.x, u4.y, u4.z, u4.w};
#pragma unroll
        for (int j = 0; j < 4; j++) {
            su[i*4 + j] = uu[j];
            mxu = max(mxu, uu[j]);
            atomicAdd(&hist[uu[j] >> 24], 1u);
        }
    }
    for (int o = 16; o; o >>= 1) mxu = max(mxu, __shfl_xor_sync(0xffffffffu, mxu, o));
    if (lane == 0) smaxw[wid] = mxu;
    __syncthreads();
    if (tid == 0) {
        unsigned m = smaxw[0];
#pragma unroll
        for (int w = 1; w < 8; w++) m = max(m, smaxw[w]);
        sh_maxu = m;
        int kk = sh_k;
        for (int b = 255; b >= 0; b--) {
            int c = (int)hist[b];
            if (kk <= c) { sh_b = b; break; }
            kk -= c;
        }
        sh_k = kk;
    }
    __syncthreads();
    unsigned b1 = (unsigned)sh_b;
    // compact pass-1 candidates
    for (int i = tid; i < S_; i += nt)
        if ((su[i] >> 24) == b1) cand[atomicAdd(&sh_cc, 1)] = (unsigned short)i;
    __syncthreads();
    int clen = sh_cc;
    __syncthreads();   // RACE FIX: all threads must read sh_cc before it is re-zeroed
    unsigned pref = b1 << 24;

    // passes at shift 16, 8, 0 over shrinking candidate list
    unsigned short* csrc = cand;
    unsigned short* cdst = cand2;
    for (int shift = 16; shift >= 0; shift -= 8) {
        if (tid < 256) hist[tid] = 0u;
        if (tid == 0) sh_cc = 0;
        __syncthreads();
        for (int i = tid; i < clen; i += nt)
            atomicAdd(&hist[(su[csrc[i]] >> shift) & 255u], 1u);
        __syncthreads();
        if (tid == 0) {
            int kk = sh_k;
            for (int b = 255; b >= 0; b--) {
                int c = (int)hist[b];
                if (kk <= c) { sh_b = b; break; }
                kk -= c;
            }
            sh_k = kk;
        }
        __syncthreads();
        unsigned bd = (unsigned)sh_b;
        pref |= bd << shift;
        if (shift > 0) {
            for (int i = tid; i < clen; i += nt) {
                unsigned short ci = csrc[i];
                if (((su[ci] >> shift) & 255u) == bd) cdst[atomicAdd(&sh_cc, 1)] = ci;
            }
            __syncthreads();
            clen = sh_cc;
            __syncthreads();   // RACE FIX: read-before-rezero barrier
            unsigned short* t = csrc; csrc = cdst; cdst = t;
        }
    }
    unsigned thr = pref;
    unsigned mu = sh_maxu;
    float mxv = (mu & 0x80000000u) ? __uint_as_float(mu ^ 0x80000000u) : __uint_as_float(~mu);

    // gather survivors + exp
    for (int i = tid; i < S_; i += nt) {
        unsigned u = su[i];
        if (u >= thr) {
            int p = atomicAdd(&sh_cnt, 1);
            if (p < 256) {
                float v = (u & 0x80000000u) ? __uint_as_float(u ^ 0x80000000u)
                                            : __uint_as_float(~u);
                sidx[p] = i;
                sval[p] = expf(v - mxv);
            }
        }
    }
    __syncthreads();
    int cnt = min(sh_cnt, 256);

    // parallel sum of exp weights
    {
        float s = 0.f;
        for (int i = tid; i < cnt; i += nt) s += sval[i];
        for (int o = 16; o; o >>= 1) s += __shfl_xor_sync(0xffffffffu, s, o);
        if (lane == 0) ssum[wid] = s;
        __syncthreads();
        if (tid == 0) {
            float t = ssum[0];
#pragma unroll
            for (int w = 1; w < 8; w++) t += ssum[w];
            sh_inv = 1.f / t;
        }
        __syncthreads();
    }

    // sparse P.V with 4-way split over survivors
    {
        int g = tid >> 6, d = tid & 63;
        const float* V = g_v + (size_t)h * S_ * DH_;
        float acc = 0.f;
        for (int i = g; i < cnt; i += 4) acc = fmaf(sval[i], V[sidx[i] * DH_ + d], acc);
        pvred[g][d] = acc;
        __syncthreads();
        if (tid < DH_) {
            float r = pvred[0][tid] + pvred[1][tid] + pvred[2][tid] + pvred[3][tid];
            g_att[q * INNER_ + h * DH_ + tid] = r * sh_inv;
        }
    }
}

// ---------------- host launcher ----------------
extern "C" void kernel_launch(void* const* d_in, const int* in_sizes, int n_in,
                              void* d_out, int out_size) {
    (void)in_sizes; (void)n_in; (void)out_size;
    const float* x    = (const float*)d_in[0];
    const float* Wqkv = (const float*)d_in[1];
    const float* Wo   = (const float*)d_in[2];
    const float* ln1g = (const float*)d_in[3];
    const float* ln1b = (const float*)d_in[4];
    const float* ln2g = (const float*)d_in[5];
    const float* ln2b = (const float*)d_in[6];
    const float* relb = (const float*)d_in[7];
    const float* w1   = (const float*)d_in[8];
    const float* b1   = (const float*)d_in[9];
    const float* w2   = (const float*)d_in[10];
    const float* b2   = (const float*)d_in[11];

    init_h_kernel<<<(S_*DIM_ + 255) / 256, 256>>>(x);
    rbT_kernel<<<16, 256>>>(relb);

    for (int l = 0; l < NL_; l++) {
        ln_kernel<<<S_, 128>>>(ln1g + l*DIM_, ln1b + l*DIM_);
        gemm128<0><<<dim3(9, 13), 256>>>(Wqkv + (size_t)l*DIM_*3*INNER_, nullptr, 3*INNER_, DIM_);
        pb_gemm<<<dim3(1, (NH_*S_)/64), 256>>>();
        scores128<<<dim3(13, 13, NH_), 256>>>();
        attn_row_kernel<<<NH_*S_, 256>>>();
        gemm128<1><<<dim3(3, 13), 256>>>(Wo + (size_t)l*INNER_*DIM_, nullptr, DIM_, INNER_);
        ln_kernel<<<S_, 128>>>(ln2g + l*DIM_, ln2b + l*DIM_);
        gemm128<2><<<dim3(12, 13), 256>>>(w1 + (size_t)l*DIM_*HID_, b1 + l*HID_, HID_, DIM_);
        gemm128<3><<<dim3(3, 13), 256>>>(w2 + (size_t)l*HID_*DIM_, b2 + l*DIM_, DIM_, HID_);
    }

    write_out_kernel<<<(S_*DIM_ + 255) / 256, 256>>>((float*)d_out);
}

// round 6
// speedup vs baseline: 1.6463x; 1.6463x over previous
#include <cuda_runtime.h>
#include <float.h>

#define S_    1600
#define DIM_  384
#define NH_   6
#define DH_   64
#define INNER_ 384
#define HID_  1536
#define NL_   6
#define GW_   40
#define TOPK_ 32
#define SCALE_ 0.05103103630798288f   // 384^-0.5

// ---------------- device scratch ----------------
__device__ float g_h[S_*DIM_];
__device__ float g_n[S_*DIM_];
__device__ float g_q[NH_*S_*DH_];
__device__ float g_k[NH_*S_*DH_];
__device__ float g_v[NH_*S_*DH_];
__device__ float g_pb[NH_*S_*64];
__device__ float g_rbT[64*64];
__device__ unsigned g_skey[(long long)NH_*S_*S_];   // monotone-uint score keys
__device__ float g_att[S_*INNER_];
__device__ float g_ff1[S_*HID_];

// ---------------- trivial kernels ----------------
__global__ void init_h_kernel(const float* __restrict__ x) {
    int i = blockIdx.x * blockDim.x + threadIdx.x;
    if (i < S_*DIM_) g_h[i] = x[i];
}
__global__ void write_out_kernel(float* __restrict__ out) {
    int i = blockIdx.x * blockDim.x + threadIdx.x;
    if (i < S_*DIM_) out[i] = g_h[i];
}
__global__ void rbT_kernel(const float* __restrict__ rb) {
    int i = blockIdx.x * blockDim.x + threadIdx.x;
    if (i < 64*64) {
        int d = i >> 6, m = i & 63;
        g_rbT[d*64 + m] = (m < 49) ? rb[m*64 + d] : 0.f;
    }
}

// ---------------- LayerNorm ----------------
__global__ void ln_kernel(const float* __restrict__ gamma, const float* __restrict__ beta) {
    int row = blockIdx.x;
    const float* x = g_h + row * DIM_;
    float s = 0.f, s2 = 0.f;
    for (int i = threadIdx.x; i < DIM_; i += blockDim.x) { float v = x[i]; s += v; s2 += v*v; }
    for (int o = 16; o; o >>= 1) {
        s  += __shfl_xor_sync(0xffffffffu, s,  o);
        s2 += __shfl_xor_sync(0xffffffffu, s2, o);
    }
    __shared__ float rs[4], rs2[4];
    int w = threadIdx.x >> 5;
    if ((threadIdx.x & 31) == 0) { rs[w] = s; rs2[w] = s2; }
    __syncthreads();
    s  = rs[0]  + rs[1]  + rs[2]  + rs[3];
    s2 = rs2[0] + rs2[1] + rs2[2] + rs2[3];
    float mean = s * (1.f / DIM_);
    float var  = s2 * (1.f / DIM_) - mean * mean;
    float inv  = rsqrtf(var + 1e-5f);
    for (int i = threadIdx.x; i < DIM_; i += blockDim.x)
        g_n[row*DIM_ + i] = (x[i] - mean) * inv * gamma[i] + beta[i];
}

// ========== double-buffered 64x64x16 SGEMM, 4x4 register tiles ==========
// MODE 0: A=g_n,   QKV scatter -> g_q/g_k/g_v
// MODE 1: A=g_att, g_h += acc
// MODE 2: A=g_n,   g_ff1 = leaky_relu(acc+bias, 0.2)
// MODE 3: A=g_ff1, g_h += acc + bias
// Requires: M multiple of 64 (1600=25*64), N multiple of 64, K multiple of 16.
template<int MODE>
__global__ void __launch_bounds__(256) gemm64db(const float* __restrict__ Bp,
                                                const float* __restrict__ bias,
                                                int N, int K) {
    const float* A = (MODE == 0 || MODE == 2) ? g_n : (MODE == 1 ? g_att : g_ff1);
    const float* B = Bp;
    __shared__ __align__(16) float As[2][16][68];
    __shared__ __align__(16) float Bs[2][16][68];
    int tid = threadIdx.x;
    int tx = tid & 15, ty = tid >> 4;
    int m0 = blockIdx.y * 64, n0 = blockIdx.x * 64;
    int arow = tid >> 2, acol = (tid & 3) * 4;
    int brow = tid >> 4, bcol = (tid & 15) * 4;
    const int nk = K >> 4;

    // preload tile 0
    {
        float4 av = *reinterpret_cast<const float4*>(A + (size_t)(m0 + arow) * K + acol);
        As[0][acol+0][arow] = av.x; As[0][acol+1][arow] = av.y;
        As[0][acol+2][arow] = av.z; As[0][acol+3][arow] = av.w;
        float4 bv = *reinterpret_cast<const float4*>(B + (size_t)brow * N + n0 + bcol);
        *reinterpret_cast<float4*>(&Bs[0][brow][bcol]) = bv;
    }
    __syncthreads();

    float acc[4][4] = {};
    for (int t = 0; t < nk; t++) {
        int cur = t & 1, nxt = cur ^ 1;
        float4 av, bv;
        bool more = (t + 1 < nk);
        if (more) {
            int k0 = (t + 1) << 4;
            av = *reinterpret_cast<const float4*>(A + (size_t)(m0 + arow) * K + k0 + acol);
            bv = *reinterpret_cast<const float4*>(B + (size_t)(k0 + brow) * N + n0 + bcol);
        }
#pragma unroll
        for (int kk = 0; kk < 16; kk++) {
            float4 a4 = *reinterpret_cast<const float4*>(&As[cur][kk][ty*4]);
            float4 b4 = *reinterpret_cast<const float4*>(&Bs[cur][kk][tx*4]);
            float ar[4] = {a4.x, a4.y, a4.z, a4.w};
            float br[4] = {b4.x, b4.y, b4.z, b4.w};
#pragma unroll
            for (int i = 0; i < 4; i++)
#pragma unroll
                for (int j = 0; j < 4; j++)
                    acc[i][j] = fmaf(ar[i], br[j], acc[i][j]);
        }
        if (more) {
            As[nxt][acol+0][arow] = av.x; As[nxt][acol+1][arow] = av.y;
            As[nxt][acol+2][arow] = av.z; As[nxt][acol+3][arow] = av.w;
            *reinterpret_cast<float4*>(&Bs[nxt][brow][bcol]) = bv;
        }
        __syncthreads();
    }

#pragma unroll
    for (int i = 0; i < 4; i++) {
        int m = m0 + ty*4 + i;
#pragma unroll
        for (int j = 0; j < 4; j++) {
            int n = n0 + tx*4 + j;
            float v = acc[i][j];
            if (MODE == 0) {
                int idx = n / 3, r = n - idx * 3;
                int hh = idx >> 6, d = idx & 63;
                float* dst = (r == 0) ? g_q : (r == 1) ? g_k : g_v;
                dst[(hh * S_ + m) * DH_ + d] = v;
            } else if (MODE == 1) {
                g_h[m * DIM_ + n] += v;
            } else if (MODE == 2) {
                float t2 = v + bias[n];
                g_ff1[m * HID_ + n] = t2 > 0.f ? t2 : 0.2f * t2;
            } else {
                g_h[m * DIM_ + n] += v + bias[n];
            }
        }
    }
}

// ---------------- pb GEMM: g_pb[9600x64] = g_q @ g_rbT ----------------
__global__ void __launch_bounds__(256) pb_gemm() {
    const float* A = g_q;
    const float* B = g_rbT;
    __shared__ __align__(16) float As[16][68];
    __shared__ __align__(16) float Bs[16][68];
    int tid = threadIdx.x;
    int tx = tid & 15, ty = tid >> 4;
    int m0 = blockIdx.y * 64;
    int arow = tid >> 2, acol = (tid & 3) * 4;
    int brow = tid >> 4, bcol = (tid & 15) * 4;
    float acc[4][4] = {};
    for (int k0 = 0; k0 < 64; k0 += 16) {
        float4 av = *reinterpret_cast<const float4*>(A + (size_t)(m0 + arow) * 64 + k0 + acol);
        As[acol+0][arow] = av.x; As[acol+1][arow] = av.y;
        As[acol+2][arow] = av.z; As[acol+3][arow] = av.w;
        float4 bv = *reinterpret_cast<const float4*>(B + (size_t)(k0 + brow) * 64 + bcol);
        *reinterpret_cast<float4*>(&Bs[brow][bcol]) = bv;
        __syncthreads();
#pragma unroll
        for (int kk = 0; kk < 16; kk++) {
            float4 a4 = *reinterpret_cast<const float4*>(&As[kk][ty*4]);
            float4 b4 = *reinterpret_cast<const float4*>(&Bs[kk][tx*4]);
            float ar[4] = {a4.x, a4.y, a4.z, a4.w};
            float br[4] = {b4.x, b4.y, b4.z, b4.w};
#pragma unroll
            for (int i = 0; i < 4; i++)
#pragma unroll
                for (int j = 0; j < 4; j++)
                    acc[i][j] = fmaf(ar[i], br[j], acc[i][j]);
        }
        __syncthreads();
    }
#pragma unroll
    for (int i = 0; i < 4; i++)
#pragma unroll
        for (int j = 0; j < 4; j++)
            g_pb[(m0 + ty*4 + i) * 64 + tx*4 + j] = acc[i][j];
}

// ---------------- scores -> monotone uint keys (double-buffered) ----------------
__global__ void __launch_bounds__(256) scores64db() {
    int h = blockIdx.z;
    const float* Q  = g_q + (size_t)h * S_ * DH_;
    const float* Km = g_k + (size_t)h * S_ * DH_;
    __shared__ __align__(16) float Qs[2][16][68];
    __shared__ __align__(16) float Ks[2][16][68];
    int tid = threadIdx.x;
    int tx = tid & 15, ty = tid >> 4;
    int m0 = blockIdx.y * 64, n0 = blockIdx.x * 64;
    int row = tid >> 2, col = (tid & 3) * 4;

    {
        float4 qv4 = *reinterpret_cast<const float4*>(Q + (size_t)(m0 + row) * DH_ + col);
        Qs[0][col+0][row] = qv4.x; Qs[0][col+1][row] = qv4.y;
        Qs[0][col+2][row] = qv4.z; Qs[0][col+3][row] = qv4.w;
        float4 kv4 = *reinterpret_cast<const float4*>(Km + (size_t)(n0 + row) * DH_ + col);
        Ks[0][col+0][row] = kv4.x; Ks[0][col+1][row] = kv4.y;
        Ks[0][col+2][row] = kv4.z; Ks[0][col+3][row] = kv4.w;
    }
    __syncthreads();

    float acc[4][4] = {};
#pragma unroll
    for (int t = 0; t < 4; t++) {
        int cur = t & 1, nxt = cur ^ 1;
        float4 qv4, kv4;
        bool more = (t + 1 < 4);
        if (more) {
            int k0 = (t + 1) << 4;
            qv4 = *reinterpret_cast<const float4*>(Q + (size_t)(m0 + row) * DH_ + k0 + col);
            kv4 = *reinterpret_cast<const float4*>(Km + (size_t)(n0 + row) * DH_ + k0 + col);
        }
#pragma unroll
        for (int kk = 0; kk < 16; kk++) {
            float4 a4 = *reinterpret_cast<const float4*>(&Qs[cur][kk][ty*4]);
            float4 b4 = *reinterpret_cast<const float4*>(&Ks[cur][kk][tx*4]);
            float ar[4] = {a4.x, a4.y, a4.z, a4.w};
            float br[4] = {b4.x, b4.y, b4.z, b4.w};
#pragma unroll
            for (int i = 0; i < 4; i++)
#pragma unroll
                for (int j = 0; j < 4; j++)
                    acc[i][j] = fmaf(ar[i], br[j], acc[i][j]);
        }
        if (more) {
            Qs[nxt][col+0][row] = qv4.x; Qs[nxt][col+1][row] = qv4.y;
            Qs[nxt][col+2][row] = qv4.z; Qs[nxt][col+3][row] = qv4.w;
            Ks[nxt][col+0][row] = kv4.x; Ks[nxt][col+1][row] = kv4.y;
            Ks[nxt][col+2][row] = kv4.z; Ks[nxt][col+3][row] = kv4.w;
        }
        __syncthreads();
    }

#pragma unroll
    for (int i = 0; i < 4; i++) {
        int q = m0 + ty*4 + i;
        int qv = q / GW_, qh = q - qv * GW_;
        const float* pbq = g_pb + ((size_t)h * S_ + q) * 64;
        float pb0 = pbq[0];
        unsigned* srow = g_skey + ((size_t)h * S_ + q) * S_;
#pragma unroll
        for (int j = 0; j < 4; j++) {
            int kq = n0 + tx*4 + j;
            int kv = kq / GW_, kh = kq - kv * GW_;
            int dv = kv - qv, dh = kh - qh;
            int ad = (dv < 0 ? -dv : dv) + (dh < 0 ? -dh : dh);
            float pbv = (ad <= 3) ? pbq[(dv + 3) * 7 + (dh + 3)] : pb0;
            float s = (acc[i][j] + pbv) * SCALE_;
            unsigned b = __float_as_uint(s);
            srow[kq] = (b & 0x80000000u) ? ~b : (b | 0x80000000u);
        }
    }
}

// ---------------- per-row: 4-pass radix select + softmax + sparse P.V ----------------
__global__ void __launch_bounds__(256) attn_row_kernel() {
    int bx = blockIdx.x;                 // h*S + q
    int h = bx / S_, q = bx - h * S_;
    const unsigned* srow = g_skey + (size_t)bx * S_;
    __shared__ unsigned su[S_];
    __shared__ unsigned hist[256];
    __shared__ int   sidx[256];
    __shared__ float sval[256];
    __shared__ float pvred[4][DH_];
    __shared__ unsigned smaxw[8];
    __shared__ float ssum[8];
    __shared__ int sh_b, sh_k, sh_cnt;
    __shared__ float sh_inv;
    __shared__ unsigned sh_maxu;
    int tid = threadIdx.x, nt = blockDim.x;
    int wid = tid >> 5, lane = tid & 31;

    // zero hist, load keys + fused pass-1 histogram + max key
    if (tid < 256) hist[tid] = 0u;
    if (tid == 0) { sh_k = TOPK_; sh_cnt = 0; }
    __syncthreads();
    unsigned mxu = 0u;
    const uint4* srow4 = reinterpret_cast<const uint4*>(srow);
    for (int i = tid; i < S_/4; i += nt) {
        uint4 u4 = srow4[i];
        unsigned uu[4] = {u4.x, u4.y, u4.z, u4.w};
#pragma unroll
        for (int j = 0; j < 4; j++) {
            su[i*4 + j] = uu[j];
            mxu = max(mxu, uu[j]);
            atomicAdd(&hist[uu[j] >> 24], 1u);
        }
    }
    for (int o = 16; o; o >>= 1) mxu = max(mxu, __shfl_xor_sync(0xffffffffu, mxu, o));
    if (lane == 0) smaxw[wid] = mxu;
    __syncthreads();
    if (tid == 0) {
        unsigned m = smaxw[0];
#pragma unroll
        for (int w = 1; w < 8; w++) m = max(m, smaxw[w]);
        sh_maxu = m;
        int kk = sh_k;
        for (int b = 255; b >= 0; b--) {
            int c = (int)hist[b];
            if (kk <= c) { sh_b = b; break; }
            kk -= c;
        }
        sh_k = kk;
    }
    __syncthreads();
    unsigned pref = ((unsigned)sh_b) << 24;

    // passes at shift 16, 8, 0 — full scan with prefix predicate
    for (int shift = 16; shift >= 0; shift -= 8) {
        if (tid < 256) hist[tid] = 0u;
        __syncthreads();
        unsigned maskhi = 0xFFFFFFFFu << (shift + 8);
        for (int i = tid; i < S_; i += nt) {
            unsigned u = su[i];
            if ((u & maskhi) == pref) atomicAdd(&hist[(u >> shift) & 255u], 1u);
        }
        __syncthreads();
        if (tid == 0) {
            int kk = sh_k;
            for (int b = 255; b >= 0; b--) {
                int c = (int)hist[b];
                if (kk <= c) { sh_b = b; break; }
                kk -= c;
            }
            sh_k = kk;
        }
        __syncthreads();
        pref |= ((unsigned)sh_b) << shift;
    }
    unsigned thr = pref;
    unsigned mu = sh_maxu;
    float mxv = (mu & 0x80000000u) ? __uint_as_float(mu ^ 0x80000000u) : __uint_as_float(~mu);

    // gather survivors + exp (score recovered from key)
    for (int i = tid; i < S_; i += nt) {
        unsigned u = su[i];
        if (u >= thr) {
            int p = atomicAdd(&sh_cnt, 1);
            if (p < 256) {
                float v = (u & 0x80000000u) ? __uint_as_float(u ^ 0x80000000u)
                                            : __uint_as_float(~u);
                sidx[p] = i;
                sval[p] = expf(v - mxv);
            }
        }
    }
    __syncthreads();
    int cnt = min(sh_cnt, 256);

    // parallel sum of exp weights
    {
        float s = 0.f;
        for (int i = tid; i < cnt; i += nt) s += sval[i];
        for (int o = 16; o; o >>= 1) s += __shfl_xor_sync(0xffffffffu, s, o);
        if (lane == 0) ssum[wid] = s;
        __syncthreads();
        if (tid == 0) {
            float t = ssum[0];
#pragma unroll
            for (int w = 1; w < 8; w++) t += ssum[w];
            sh_inv = 1.f / t;
        }
        __syncthreads();
    }

    // sparse P.V with 4-way split over survivors
    {
        int g = tid >> 6, d = tid & 63;
        const float* V = g_v + (size_t)h * S_ * DH_;
        float acc = 0.f;
        for (int i = g; i < cnt; i += 4) acc = fmaf(sval[i], V[sidx[i] * DH_ + d], acc);
        pvred[g][d] = acc;
        __syncthreads();
        if (tid < DH_) {
            float r = pvred[0][tid] + pvred[1][tid] + pvred[2][tid] + pvred[3][tid];
            g_att[q * INNER_ + h * DH_ + tid] = r * sh_inv;
        }
    }
}

// ---------------- host launcher ----------------
extern "C" void kernel_launch(void* const* d_in, const int* in_sizes, int n_in,
                              void* d_out, int out_size) {
    (void)in_sizes; (void)n_in; (void)out_size;
    const float* x    = (const float*)d_in[0];
    const float* Wqkv = (const float*)d_in[1];
    const float* Wo   = (const float*)d_in[2];
    const float* ln1g = (const float*)d_in[3];
    const float* ln1b = (const float*)d_in[4];
    const float* ln2g = (const float*)d_in[5];
    const float* ln2b = (const float*)d_in[6];
    const float* relb = (const float*)d_in[7];
    const float* w1   = (const float*)d_in[8];
    const float* b1   = (const float*)d_in[9];
    const float* w2   = (const float*)d_in[10];
    const float* b2   = (const float*)d_in[11];

    init_h_kernel<<<(S_*DIM_ + 255) / 256, 256>>>(x);
    rbT_kernel<<<16, 256>>>(relb);

    for (int l = 0; l < NL_; l++) {
        ln_kernel<<<S_, 128>>>(ln1g + l*DIM_, ln1b + l*DIM_);
        gemm64db<0><<<dim3(18, 25), 256>>>(Wqkv + (size_t)l*DIM_*3*INNER_, nullptr, 3*INNER_, DIM_);
        pb_gemm<<<dim3(1, (NH_*S_)/64), 256>>>();
        scores64db<<<dim3(25, 25, NH_), 256>>>();
        attn_row_kernel<<<NH_*S_, 256>>>();
        gemm64db<1><<<dim3(6, 25), 256>>>(Wo + (size_t)l*INNER_*DIM_, nullptr, DIM_, INNER_);
        ln_kernel<<<S_, 128>>>(ln2g + l*DIM_, ln2b + l*DIM_);
        gemm64db<2><<<dim3(24, 25), 256>>>(w1 + (size_t)l*DIM_*HID_, b1 + l*HID_, HID_, DIM_);
        gemm64db<3><<<dim3(6, 25), 256>>>(w2 + (size_t)l*HID_*DIM_, b2 + l*DIM_, DIM_, HID_);
    }

    write_out_kernel<<<(S_*DIM_ + 255) / 256, 256>>>((float*)d_out);
}

// round 7
// speedup vs baseline: 1.6716x; 1.0154x over previous
#include <cuda_runtime.h>
#include <float.h>

#define S_    1600
#define DIM_  384
#define NH_   6
#define DH_   64
#define INNER_ 384
#define HID_  1536
#define NL_   6
#define GW_   40
#define TOPK_ 32
#define SCALE_ 0.05103103630798288f   // 384^-0.5

// ---------------- device scratch ----------------
__device__ float g_h[S_*DIM_];
__device__ float g_n[S_*DIM_];
__device__ float g_q[NH_*S_*DH_];
__device__ float g_k[NH_*S_*DH_];
__device__ float g_v[NH_*S_*DH_];
__device__ float g_pb[NH_*S_*64];
__device__ float g_rbT[64*64];
__device__ unsigned g_skey[(long long)NH_*S_*S_];
__device__ float g_att[S_*INNER_];
__device__ float g_ff1[S_*HID_];

// ---------------- trivial kernels ----------------
__global__ void init_h_kernel(const float* __restrict__ x) {
    int i = blockIdx.x * blockDim.x + threadIdx.x;
    if (i < S_*DIM_) g_h[i] = x[i];
}
__global__ void write_out_kernel(float* __restrict__ out) {
    int i = blockIdx.x * blockDim.x + threadIdx.x;
    if (i < S_*DIM_) out[i] = g_h[i];
}
__global__ void rbT_kernel(const float* __restrict__ rb) {
    int i = blockIdx.x * blockDim.x + threadIdx.x;
    if (i < 64*64) {
        int d = i >> 6, m = i & 63;
        g_rbT[d*64 + m] = (m < 49) ? rb[m*64 + d] : 0.f;
    }
}

// ---------------- LayerNorm ----------------
__global__ void ln_kernel(const float* __restrict__ gamma, const float* __restrict__ beta) {
    int row = blockIdx.x;
    const float* x = g_h + row * DIM_;
    float s = 0.f, s2 = 0.f;
    for (int i = threadIdx.x; i < DIM_; i += blockDim.x) { float v = x[i]; s += v; s2 += v*v; }
    for (int o = 16; o; o >>= 1) {
        s  += __shfl_xor_sync(0xffffffffu, s,  o);
        s2 += __shfl_xor_sync(0xffffffffu, s2, o);
    }
    __shared__ float rs[4], rs2[4];
    int w = threadIdx.x >> 5;
    if ((threadIdx.x & 31) == 0) { rs[w] = s; rs2[w] = s2; }
    __syncthreads();
    s  = rs[0]  + rs[1]  + rs[2]  + rs[3];
    s2 = rs2[0] + rs2[1] + rs2[2] + rs2[3];
    float mean = s * (1.f / DIM_);
    float var  = s2 * (1.f / DIM_) - mean * mean;
    float inv  = rsqrtf(var + 1e-5f);
    for (int i = threadIdx.x; i < DIM_; i += blockDim.x)
        g_n[row*DIM_ + i] = (x[i] - mean) * inv * gamma[i] + beta[i];
}

// ========== double-buffered 64x64x16 SGEMM (4x4/thread) — Wo, FF2 ==========
// MODE 1: A=g_att, g_h += acc ;  MODE 3: A=g_ff1, g_h += acc + bias
template<int MODE>
__global__ void __launch_bounds__(256) gemm64db(const float* __restrict__ B,
                                                const float* __restrict__ bias,
                                                int N, int K) {
    const float* A = (MODE == 1) ? g_att : g_ff1;
    __shared__ __align__(16) float As[2][16][68];
    __shared__ __align__(16) float Bs[2][16][68];
    int tid = threadIdx.x;
    int tx = tid & 15, ty = tid >> 4;
    int m0 = blockIdx.y * 64, n0 = blockIdx.x * 64;
    int arow = tid >> 2, acol = (tid & 3) * 4;
    int brow = tid >> 4, bcol = (tid & 15) * 4;
    const int nk = K >> 4;
    {
        float4 av = *reinterpret_cast<const float4*>(A + (size_t)(m0 + arow) * K + acol);
        As[0][acol+0][arow] = av.x; As[0][acol+1][arow] = av.y;
        As[0][acol+2][arow] = av.z; As[0][acol+3][arow] = av.w;
        float4 bv = *reinterpret_cast<const float4*>(B + (size_t)brow * N + n0 + bcol);
        *reinterpret_cast<float4*>(&Bs[0][brow][bcol]) = bv;
    }
    __syncthreads();
    float acc[4][4] = {};
    for (int t = 0; t < nk; t++) {
        int cur = t & 1, nxt = cur ^ 1;
        float4 av, bv;
        bool more = (t + 1 < nk);
        if (more) {
            int k0 = (t + 1) << 4;
            av = *reinterpret_cast<const float4*>(A + (size_t)(m0 + arow) * K + k0 + acol);
            bv = *reinterpret_cast<const float4*>(B + (size_t)(k0 + brow) * N + n0 + bcol);
        }
#pragma unroll
        for (int kk = 0; kk < 16; kk++) {
            float4 a4 = *reinterpret_cast<const float4*>(&As[cur][kk][ty*4]);
            float4 b4 = *reinterpret_cast<const float4*>(&Bs[cur][kk][tx*4]);
            float ar[4] = {a4.x, a4.y, a4.z, a4.w};
            float br[4] = {b4.x, b4.y, b4.z, b4.w};
#pragma unroll
            for (int i = 0; i < 4; i++)
#pragma unroll
                for (int j = 0; j < 4; j++)
                    acc[i][j] = fmaf(ar[i], br[j], acc[i][j]);
        }
        if (more) {
            As[nxt][acol+0][arow] = av.x; As[nxt][acol+1][arow] = av.y;
            As[nxt][acol+2][arow] = av.z; As[nxt][acol+3][arow] = av.w;
            *reinterpret_cast<float4*>(&Bs[nxt][brow][bcol]) = bv;
        }
        __syncthreads();
    }
#pragma unroll
    for (int i = 0; i < 4; i++) {
        int m = m0 + ty*4 + i;
#pragma unroll
        for (int j = 0; j < 4; j++) {
            int n = n0 + tx*4 + j;
            if (MODE == 1) g_h[m * DIM_ + n] += acc[i][j];
            else           g_h[m * DIM_ + n] += acc[i][j] + bias[n];
        }
    }
}

// ========== double-buffered 64x128x16 SGEMM (4x8/thread) — QKV, FF1 ==========
// MODE 0: QKV scatter ; MODE 2: g_ff1 = leaky_relu(acc+bias)
template<int MODE>
__global__ void __launch_bounds__(256) gemmW(const float* __restrict__ B,
                                             const float* __restrict__ bias,
                                             int N, int K) {
    const float* A = g_n;
    __shared__ __align__(16) float As[2][16][68];
    __shared__ __align__(16) float Bs[2][16][136];
    int tid = threadIdx.x;
    int tx = tid & 15, ty = tid >> 4;
    int m0 = blockIdx.y * 64, n0 = blockIdx.x * 128;
    int arow = tid >> 2, acol = (tid & 3) * 4;
    int br = tid >> 5, bc = (tid & 31) * 4;
    const int nk = K >> 4;
    {
        float4 av = *reinterpret_cast<const float4*>(A + (size_t)(m0 + arow) * K + acol);
        As[0][acol+0][arow] = av.x; As[0][acol+1][arow] = av.y;
        As[0][acol+2][arow] = av.z; As[0][acol+3][arow] = av.w;
        float4 b0 = *reinterpret_cast<const float4*>(B + (size_t)br * N + n0 + bc);
        float4 b1 = *reinterpret_cast<const float4*>(B + (size_t)(br + 8) * N + n0 + bc);
        *reinterpret_cast<float4*>(&Bs[0][br][bc]) = b0;
        *reinterpret_cast<float4*>(&Bs[0][br+8][bc]) = b1;
    }
    __syncthreads();
    float acc[4][8] = {};
    for (int t = 0; t < nk; t++) {
        int cur = t & 1, nxt = cur ^ 1;
        float4 av, b0, b1;
        bool more = (t + 1 < nk);
        if (more) {
            int k0 = (t + 1) << 4;
            av = *reinterpret_cast<const float4*>(A + (size_t)(m0 + arow) * K + k0 + acol);
            b0 = *reinterpret_cast<const float4*>(B + (size_t)(k0 + br) * N + n0 + bc);
            b1 = *reinterpret_cast<const float4*>(B + (size_t)(k0 + br + 8) * N + n0 + bc);
        }
#pragma unroll
        for (int kk = 0; kk < 16; kk++) {
            float4 a4 = *reinterpret_cast<const float4*>(&As[cur][kk][ty*4]);
            float4 c0 = *reinterpret_cast<const float4*>(&Bs[cur][kk][tx*8]);
            float4 c1 = *reinterpret_cast<const float4*>(&Bs[cur][kk][tx*8+4]);
            float ar[4] = {a4.x, a4.y, a4.z, a4.w};
            float brv[8] = {c0.x, c0.y, c0.z, c0.w, c1.x, c1.y, c1.z, c1.w};
#pragma unroll
            for (int i = 0; i < 4; i++)
#pragma unroll
                for (int j = 0; j < 8; j++)
                    acc[i][j] = fmaf(ar[i], brv[j], acc[i][j]);
        }
        if (more) {
            As[nxt][acol+0][arow] = av.x; As[nxt][acol+1][arow] = av.y;
            As[nxt][acol+2][arow] = av.z; As[nxt][acol+3][arow] = av.w;
            *reinterpret_cast<float4*>(&Bs[nxt][br][bc]) = b0;
            *reinterpret_cast<float4*>(&Bs[nxt][br+8][bc]) = b1;
        }
        __syncthreads();
    }
#pragma unroll
    for (int i = 0; i < 4; i++) {
        int m = m0 + ty*4 + i;
#pragma unroll
        for (int j = 0; j < 8; j++) {
            int n = n0 + tx*8 + j;
            float v = acc[i][j];
            if (MODE == 0) {
                int idx = n / 3, r = n - idx * 3;
                int hh = idx >> 6, d = idx & 63;
                float* dst = (r == 0) ? g_q : (r == 1) ? g_k : g_v;
                dst[(hh * S_ + m) * DH_ + d] = v;
            } else {
                float t2 = v + bias[n];
                g_ff1[m * HID_ + n] = t2 > 0.f ? t2 : 0.2f * t2;
            }
        }
    }
}

// ---------------- pb GEMM: g_pb[9600x64] = g_q @ g_rbT ----------------
__global__ void __launch_bounds__(256) pb_gemm() {
    const float* A = g_q;
    const float* B = g_rbT;
    __shared__ __align__(16) float As[16][68];
    __shared__ __align__(16) float Bs[16][68];
    int tid = threadIdx.x;
    int tx = tid & 15, ty = tid >> 4;
    int m0 = blockIdx.y * 64;
    int arow = tid >> 2, acol = (tid & 3) * 4;
    int brow = tid >> 4, bcol = (tid & 15) * 4;
    float acc[4][4] = {};
    for (int k0 = 0; k0 < 64; k0 += 16) {
        float4 av = *reinterpret_cast<const float4*>(A + (size_t)(m0 + arow) * 64 + k0 + acol);
        As[acol+0][arow] = av.x; As[acol+1][arow] = av.y;
        As[acol+2][arow] = av.z; As[acol+3][arow] = av.w;
        float4 bv = *reinterpret_cast<const float4*>(B + (size_t)(k0 + brow) * 64 + bcol);
        *reinterpret_cast<float4*>(&Bs[brow][bcol]) = bv;
        __syncthreads();
#pragma unroll
        for (int kk = 0; kk < 16; kk++) {
            float4 a4 = *reinterpret_cast<const float4*>(&As[kk][ty*4]);
            float4 b4 = *reinterpret_cast<const float4*>(&Bs[kk][tx*4]);
            float ar[4] = {a4.x, a4.y, a4.z, a4.w};
            float br[4] = {b4.x, b4.y, b4.z, b4.w};
#pragma unroll
            for (int i = 0; i < 4; i++)
#pragma unroll
                for (int j = 0; j < 4; j++)
                    acc[i][j] = fmaf(ar[i], br[j], acc[i][j]);
        }
        __syncthreads();
    }
#pragma unroll
    for (int i = 0; i < 4; i++)
#pragma unroll
        for (int j = 0; j < 4; j++)
            g_pb[(m0 + ty*4 + i) * 64 + tx*4 + j] = acc[i][j];
}

// ---------------- scores -> monotone uint keys (double-buffered 64x64) ----------------
__global__ void __launch_bounds__(256) scores64db() {
    int h = blockIdx.z;
    const float* Q  = g_q + (size_t)h * S_ * DH_;
    const float* Km = g_k + (size_t)h * S_ * DH_;
    __shared__ __align__(16) float Qs[2][16][68];
    __shared__ __align__(16) float Ks[2][16][68];
    int tid = threadIdx.x;
    int tx = tid & 15, ty = tid >> 4;
    int m0 = blockIdx.y * 64, n0 = blockIdx.x * 64;
    int row = tid >> 2, col = (tid & 3) * 4;
    {
        float4 qv4 = *reinterpret_cast<const float4*>(Q + (size_t)(m0 + row) * DH_ + col);
        Qs[0][col+0][row] = qv4.x; Qs[0][col+1][row] = qv4.y;
        Qs[0][col+2][row] = qv4.z; Qs[0][col+3][row] = qv4.w;
        float4 kv4 = *reinterpret_cast<const float4*>(Km + (size_t)(n0 + row) * DH_ + col);
        Ks[0][col+0][row] = kv4.x; Ks[0][col+1][row] = kv4.y;
        Ks[0][col+2][row] = kv4.z; Ks[0][col+3][row] = kv4.w;
    }
    __syncthreads();
    float acc[4][4] = {};
#pragma unroll
    for (int t = 0; t < 4; t++) {
        int cur = t & 1, nxt = cur ^ 1;
        float4 qv4, kv4;
        bool more = (t + 1 < 4);
        if (more) {
            int k0 = (t + 1) << 4;
            qv4 = *reinterpret_cast<const float4*>(Q + (size_t)(m0 + row) * DH_ + k0 + col);
            kv4 = *reinterpret_cast<const float4*>(Km + (size_t)(n0 + row) * DH_ + k0 + col);
        }
#pragma unroll
        for (int kk = 0; kk < 16; kk++) {
            float4 a4 = *reinterpret_cast<const float4*>(&Qs[cur][kk][ty*4]);
            float4 b4 = *reinterpret_cast<const float4*>(&Ks[cur][kk][tx*4]);
            float ar[4] = {a4.x, a4.y, a4.z, a4.w};
            float br[4] = {b4.x, b4.y, b4.z, b4.w};
#pragma unroll
            for (int i = 0; i < 4; i++)
#pragma unroll
                for (int j = 0; j < 4; j++)
                    acc[i][j] = fmaf(ar[i], br[j], acc[i][j]);
        }
        if (more) {
            Qs[nxt][col+0][row] = qv4.x; Qs[nxt][col+1][row] = qv4.y;
            Qs[nxt][col+2][row] = qv4.z; Qs[nxt][col+3][row] = qv4.w;
            Ks[nxt][col+0][row] = kv4.x; Ks[nxt][col+1][row] = kv4.y;
            Ks[nxt][col+2][row] = kv4.z; Ks[nxt][col+3][row] = kv4.w;
        }
        __syncthreads();
    }
#pragma unroll
    for (int i = 0; i < 4; i++) {
        int q = m0 + ty*4 + i;
        int qv = q / GW_, qh = q - qv * GW_;
        const float* pbq = g_pb + ((size_t)h * S_ + q) * 64;
        float pb0 = pbq[0];
        unsigned* srow = g_skey + ((size_t)h * S_ + q) * S_;
#pragma unroll
        for (int j = 0; j < 4; j++) {
            int kq = n0 + tx*4 + j;
            int kv = kq / GW_, kh = kq - kv * GW_;
            int dv = kv - qv, dh = kh - qh;
            int ad = (dv < 0 ? -dv : dv) + (dh < 0 ? -dh : dh);
            float pbv = (ad <= 3) ? pbq[(dv + 3) * 7 + (dh + 3)] : pb0;
            float s = (acc[i][j] + pbv) * SCALE_;
            unsigned b = __float_as_uint(s);
            srow[kq] = (b & 0x80000000u) ? ~b : (b | 0x80000000u);
        }
    }
}

// ---------------- attn_row: register keys + warp-aggregated hist + parallel select ----------------
__global__ void __launch_bounds__(256) attn_row_kernel() {
    int bx = blockIdx.x;                 // h*S + q
    int h = bx / S_, q = bx - h * S_;
    const unsigned* srow = g_skey + (size_t)bx * S_;
    __shared__ unsigned hist[256];
    __shared__ unsigned sufw[8];
    __shared__ int   sidx[256];
    __shared__ float sval[256];
    __shared__ float pvred[4][DH_];
    __shared__ unsigned smaxw[8];
    __shared__ float ssum[8];
    __shared__ int sh_b, sh_k, sh_k2, sh_cnt;
    __shared__ float sh_inv;
    __shared__ unsigned sh_maxu;
    int tid = threadIdx.x;
    int wid = tid >> 5, lane = tid & 31;

    // keys in registers: key[j] = srow[tid + j*256]; S = 6*256 + 64
    unsigned key[7];
    int nkk = (tid < 64) ? 7 : 6;
#pragma unroll
    for (int j = 0; j < 6; j++) key[j] = srow[tid + j*256];
    key[6] = (tid < 64) ? srow[tid + 1536] : 0u;

    // block max key
    unsigned mxu = 0u;
#pragma unroll
    for (int j = 0; j < 7; j++) mxu = max(mxu, key[j]);   // key[6]=0 for invalid: harmless
    for (int o = 16; o; o >>= 1) mxu = max(mxu, __shfl_xor_sync(0xffffffffu, mxu, o));
    if (lane == 0) smaxw[wid] = mxu;
    if (tid == 0) { sh_k = TOPK_; sh_cnt = 0; }
    __syncthreads();
    if (tid == 0) {
        unsigned m = smaxw[0];
#pragma unroll
        for (int w = 1; w < 8; w++) m = max(m, smaxw[w]);
        sh_maxu = m;
    }

    // 4-pass radix select, warp-aggregated histogram, parallel suffix select
    unsigned pref = 0u;
    for (int shift = 24; shift >= 0; shift -= 8) {
        hist[tid] = 0u;
        __syncthreads();
        unsigned maskhi = (shift == 24) ? 0u : (0xFFFFFFFFu << (shift + 8));
        for (int j = 0; j < nkk; j++) {
            unsigned u = key[j];
            if ((u & maskhi) == pref) {
                unsigned b = (u >> shift) & 255u;
                unsigned act = __activemask();
                unsigned mmask = __match_any_sync(act, b);
                int leader = __ffs(mmask) - 1;
                if (lane == leader) atomicAdd(&hist[b], (unsigned)__popc(mmask));
            }
        }
        __syncthreads();
        // parallel suffix sums over 256 bins
        unsigned c = hist[tid];
        unsigned s = c;
#pragma unroll
        for (int o = 1; o < 32; o <<= 1) {
            unsigned t = __shfl_down_sync(0xffffffffu, s, o);
            if (lane + o < 32) s += t;
        }
        if (lane == 0) sufw[wid] = s;
        __syncthreads();
        unsigned add = 0;
        for (int w = wid + 1; w < 8; w++) add += sufw[w];
        unsigned suf_incl = s + add;          // count of keys in bins >= tid
        unsigned suf_excl = suf_incl - c;     // count in bins > tid
        unsigned kkr = (unsigned)sh_k;
        if (suf_incl >= kkr && suf_excl < kkr) { sh_b = tid; sh_k2 = (int)(kkr - suf_excl); }
        __syncthreads();
        pref |= ((unsigned)sh_b) << shift;
        if (tid == 0) sh_k = sh_k2;
        __syncthreads();
    }
    unsigned thr = pref;
    unsigned mu = sh_maxu;
    float mxv = (mu & 0x80000000u) ? __uint_as_float(mu ^ 0x80000000u) : __uint_as_float(~mu);

    // gather survivors + exp (score recovered from key)
    for (int j = 0; j < nkk; j++) {
        unsigned u = key[j];
        if (u >= thr) {
            int p = atomicAdd(&sh_cnt, 1);
            if (p < 256) {
                float v = (u & 0x80000000u) ? __uint_as_float(u ^ 0x80000000u)
                                            : __uint_as_float(~u);
                sidx[p] = tid + j*256;
                sval[p] = expf(v - mxv);
            }
        }
    }
    __syncthreads();
    int cnt = min(sh_cnt, 256);

    // parallel sum of exp weights
    {
        float s = 0.f;
        for (int i = tid; i < cnt; i += 256) s += sval[i];
        for (int o = 16; o; o >>= 1) s += __shfl_xor_sync(0xffffffffu, s, o);
        if (lane == 0) ssum[wid] = s;
        __syncthreads();
        if (tid == 0) {
            float t = ssum[0];
#pragma unroll
            for (int w = 1; w < 8; w++) t += ssum[w];
            sh_inv = 1.f / t;
        }
        __syncthreads();
    }

    // sparse P.V with 4-way split over survivors
    {
        int g = tid >> 6, d = tid & 63;
        const float* V = g_v + (size_t)h * S_ * DH_;
        float acc = 0.f;
        for (int i = g; i < cnt; i += 4) acc = fmaf(sval[i], V[sidx[i] * DH_ + d], acc);
        pvred[g][d] = acc;
        __syncthreads();
        if (tid < DH_) {
            float r = pvred[0][tid] + pvred[1][tid] + pvred[2][tid] + pvred[3][tid];
            g_att[q * INNER_ + h * DH_ + tid] = r * sh_inv;
        }
    }
}

// ---------------- host launcher ----------------
extern "C" void kernel_launch(void* const* d_in, const int* in_sizes, int n_in,
                              void* d_out, int out_size) {
    (void)in_sizes; (void)n_in; (void)out_size;
    const float* x    = (const float*)d_in[0];
    const float* Wqkv = (const float*)d_in[1];
    const float* Wo   = (const float*)d_in[2];
    const float* ln1g = (const float*)d_in[3];
    const float* ln1b = (const float*)d_in[4];
    const float* ln2g = (const float*)d_in[5];
    const float* ln2b = (const float*)d_in[6];
    const float* relb = (const float*)d_in[7];
    const float* w1   = (const float*)d_in[8];
    const float* b1   = (const float*)d_in[9];
    const float* w2   = (const float*)d_in[10];
    const float* b2   = (const float*)d_in[11];

    init_h_kernel<<<(S_*DIM_ + 255) / 256, 256>>>(x);
    rbT_kernel<<<16, 256>>>(relb);

    for (int l = 0; l < NL_; l++) {
        ln_kernel<<<S_, 128>>>(ln1g + l*DIM_, ln1b + l*DIM_);
        gemmW<0><<<dim3(9, 25), 256>>>(Wqkv + (size_t)l*DIM_*3*INNER_, nullptr, 3*INNER_, DIM_);
        pb_gemm<<<dim3(1, (NH_*S_)/64), 256>>>();
        scores64db<<<dim3(25, 25, NH_), 256>>>();
        attn_row_kernel<<<NH_*S_, 256>>>();
        gemm64db<1><<<dim3(6, 25), 256>>>(Wo + (size_t)l*INNER_*DIM_, nullptr, DIM_, INNER_);
        ln_kernel<<<S_, 128>>>(ln2g + l*DIM_, ln2b + l*DIM_);
        gemmW<2><<<dim3(12, 25), 256>>>(w1 + (size_t)l*DIM_*HID_, b1 + l*HID_, HID_, DIM_);
        gemm64db<3><<<dim3(6, 25), 256>>>(w2 + (size_t)l*HID_*DIM_, b2 + l*DIM_, DIM_, HID_);
    }

    write_out_kernel<<<(S_*DIM_ + 255) / 256, 256>>>((float*)d_out);
}

// round 8
// speedup vs baseline: 1.9675x; 1.1770x over previous
#include <cuda_runtime.h>
#include <float.h>

#define S_    1600
#define DIM_  384
#define NH_   6
#define DH_   64
#define INNER_ 384
#define HID_  1536
#define NL_   6
#define GW_   40
#define TOPK_ 32
#define SCALE_ 0.05103103630798288f   // 384^-0.5

// ---------------- device scratch ----------------
__device__ float g_h[S_*DIM_];
__device__ float g_n[S_*DIM_];
__device__ float g_q[NH_*S_*DH_];
__device__ float g_k[NH_*S_*DH_];
__device__ float g_v[NH_*S_*DH_];
__device__ float g_pb[NH_*S_*64];
__device__ float g_rbT[64*64];
__device__ unsigned g_skey[(long long)NH_*S_*S_];
__device__ float g_att[S_*INNER_];
__device__ float g_ff1[S_*HID_];

// ---------------- trivial kernels ----------------
__global__ void init_h_kernel(const float* __restrict__ x) {
    int i = blockIdx.x * blockDim.x + threadIdx.x;
    if (i < S_*DIM_) g_h[i] = x[i];
}
__global__ void write_out_kernel(float* __restrict__ out) {
    int i = blockIdx.x * blockDim.x + threadIdx.x;
    if (i < S_*DIM_) out[i] = g_h[i];
}
__global__ void rbT_kernel(const float* __restrict__ rb) {
    int i = blockIdx.x * blockDim.x + threadIdx.x;
    if (i < 64*64) {
        int d = i >> 6, m = i & 63;
        g_rbT[d*64 + m] = (m < 49) ? rb[m*64 + d] : 0.f;
    }
}

// ---------------- LayerNorm ----------------
__global__ void ln_kernel(const float* __restrict__ gamma, const float* __restrict__ beta) {
    int row = blockIdx.x;
    const float* x = g_h + row * DIM_;
    float s = 0.f, s2 = 0.f;
    for (int i = threadIdx.x; i < DIM_; i += blockDim.x) { float v = x[i]; s += v; s2 += v*v; }
    for (int o = 16; o; o >>= 1) {
        s  += __shfl_xor_sync(0xffffffffu, s,  o);
        s2 += __shfl_xor_sync(0xffffffffu, s2, o);
    }
    __shared__ float rs[4], rs2[4];
    int w = threadIdx.x >> 5;
    if ((threadIdx.x & 31) == 0) { rs[w] = s; rs2[w] = s2; }
    __syncthreads();
    s  = rs[0]  + rs[1]  + rs[2]  + rs[3];
    s2 = rs2[0] + rs2[1] + rs2[2] + rs2[3];
    float mean = s * (1.f / DIM_);
    float var  = s2 * (1.f / DIM_) - mean * mean;
    float inv  = rsqrtf(var + 1e-5f);
    for (int i = threadIdx.x; i < DIM_; i += blockDim.x)
        g_n[row*DIM_ + i] = (x[i] - mean) * inv * gamma[i] + beta[i];
}

// ========== double-buffered 64x64x16 SGEMM, 4x4 register tiles ==========
// MODE 0: A=g_n,   QKV scatter -> g_q/g_k/g_v
// MODE 1: A=g_att, g_h += acc
// MODE 2: A=g_n,   g_ff1 = leaky_relu(acc+bias, 0.2)
// MODE 3: A=g_ff1, g_h += acc + bias
template<int MODE>
__global__ void __launch_bounds__(256) gemm64db(const float* __restrict__ B,
                                                const float* __restrict__ bias,
                                                int N, int K) {
    const float* A = (MODE == 0 || MODE == 2) ? g_n : (MODE == 1 ? g_att : g_ff1);
    __shared__ __align__(16) float As[2][16][68];
    __shared__ __align__(16) float Bs[2][16][68];
    int tid = threadIdx.x;
    int tx = tid & 15, ty = tid >> 4;
    int m0 = blockIdx.y * 64, n0 = blockIdx.x * 64;
    int arow = tid >> 2, acol = (tid & 3) * 4;
    int brow = tid >> 4, bcol = (tid & 15) * 4;
    const int nk = K >> 4;
    {
        float4 av = *reinterpret_cast<const float4*>(A + (size_t)(m0 + arow) * K + acol);
        As[0][acol+0][arow] = av.x; As[0][acol+1][arow] = av.y;
        As[0][acol+2][arow] = av.z; As[0][acol+3][arow] = av.w;
        float4 bv = *reinterpret_cast<const float4*>(B + (size_t)brow * N + n0 + bcol);
        *reinterpret_cast<float4*>(&Bs[0][brow][bcol]) = bv;
    }
    __syncthreads();
    float acc[4][4] = {};
    for (int t = 0; t < nk; t++) {
        int cur = t & 1, nxt = cur ^ 1;
        float4 av, bv;
        bool more = (t + 1 < nk);
        if (more) {
            int k0 = (t + 1) << 4;
            av = *reinterpret_cast<const float4*>(A + (size_t)(m0 + arow) * K + k0 + acol);
            bv = *reinterpret_cast<const float4*>(B + (size_t)(k0 + brow) * N + n0 + bcol);
        }
#pragma unroll
        for (int kk = 0; kk < 16; kk++) {
            float4 a4 = *reinterpret_cast<const float4*>(&As[cur][kk][ty*4]);
            float4 b4 = *reinterpret_cast<const float4*>(&Bs[cur][kk][tx*4]);
            float ar[4] = {a4.x, a4.y, a4.z, a4.w};
            float br[4] = {b4.x, b4.y, b4.z, b4.w};
#pragma unroll
            for (int i = 0; i < 4; i++)
#pragma unroll
                for (int j = 0; j < 4; j++)
                    acc[i][j] = fmaf(ar[i], br[j], acc[i][j]);
        }
        if (more) {
            As[nxt][acol+0][arow] = av.x; As[nxt][acol+1][arow] = av.y;
            As[nxt][acol+2][arow] = av.z; As[nxt][acol+3][arow] = av.w;
            *reinterpret_cast<float4*>(&Bs[nxt][brow][bcol]) = bv;
        }
        __syncthreads();
    }
#pragma unroll
    for (int i = 0; i < 4; i++) {
        int m = m0 + ty*4 + i;
#pragma unroll
        for (int j = 0; j < 4; j++) {
            int n = n0 + tx*4 + j;
            float v = acc[i][j];
            if (MODE == 0) {
                int idx = n / 3, r = n - idx * 3;
                int hh = idx >> 6, d = idx & 63;
                float* dst = (r == 0) ? g_q : (r == 1) ? g_k : g_v;
                dst[(hh * S_ + m) * DH_ + d] = v;
            } else if (MODE == 1) {
                g_h[m * DIM_ + n] += v;
            } else if (MODE == 2) {
                float t2 = v + bias[n];
                g_ff1[m * HID_ + n] = t2 > 0.f ? t2 : 0.2f * t2;
            } else {
                g_h[m * DIM_ + n] += v + bias[n];
            }
        }
    }
}

// ---------------- pb GEMM: g_pb[9600x64] = g_q @ g_rbT ----------------
__global__ void __launch_bounds__(256) pb_gemm() {
    const float* A = g_q;
    const float* B = g_rbT;
    __shared__ __align__(16) float As[16][68];
    __shared__ __align__(16) float Bs[16][68];
    int tid = threadIdx.x;
    int tx = tid & 15, ty = tid >> 4;
    int m0 = blockIdx.y * 64;
    int arow = tid >> 2, acol = (tid & 3) * 4;
    int brow = tid >> 4, bcol = (tid & 15) * 4;
    float acc[4][4] = {};
    for (int k0 = 0; k0 < 64; k0 += 16) {
        float4 av = *reinterpret_cast<const float4*>(A + (size_t)(m0 + arow) * 64 + k0 + acol);
        As[acol+0][arow] = av.x; As[acol+1][arow] = av.y;
        As[acol+2][arow] = av.z; As[acol+3][arow] = av.w;
        float4 bv = *reinterpret_cast<const float4*>(B + (size_t)(k0 + brow) * 64 + bcol);
        *reinterpret_cast<float4*>(&Bs[brow][bcol]) = bv;
        __syncthreads();
#pragma unroll
        for (int kk = 0; kk < 16; kk++) {
            float4 a4 = *reinterpret_cast<const float4*>(&As[kk][ty*4]);
            float4 b4 = *reinterpret_cast<const float4*>(&Bs[kk][tx*4]);
            float ar[4] = {a4.x, a4.y, a4.z, a4.w};
            float br[4] = {b4.x, b4.y, b4.z, b4.w};
#pragma unroll
            for (int i = 0; i < 4; i++)
#pragma unroll
                for (int j = 0; j < 4; j++)
                    acc[i][j] = fmaf(ar[i], br[j], acc[i][j]);
        }
        __syncthreads();
    }
#pragma unroll
    for (int i = 0; i < 4; i++)
#pragma unroll
        for (int j = 0; j < 4; j++)
            g_pb[(m0 + ty*4 + i) * 64 + tx*4 + j] = acc[i][j];
}

// ---------------- scores -> monotone uint keys (double-buffered 64x64) ----------------
__global__ void __launch_bounds__(256) scores64db() {
    int h = blockIdx.z;
    const float* Q  = g_q + (size_t)h * S_ * DH_;
    const float* Km = g_k + (size_t)h * S_ * DH_;
    __shared__ __align__(16) float Qs[2][16][68];
    __shared__ __align__(16) float Ks[2][16][68];
    int tid = threadIdx.x;
    int tx = tid & 15, ty = tid >> 4;
    int m0 = blockIdx.y * 64, n0 = blockIdx.x * 64;
    int row = tid >> 2, col = (tid & 3) * 4;
    {
        float4 qv4 = *reinterpret_cast<const float4*>(Q + (size_t)(m0 + row) * DH_ + col);
        Qs[0][col+0][row] = qv4.x; Qs[0][col+1][row] = qv4.y;
        Qs[0][col+2][row] = qv4.z; Qs[0][col+3][row] = qv4.w;
        float4 kv4 = *reinterpret_cast<const float4*>(Km + (size_t)(n0 + row) * DH_ + col);
        Ks[0][col+0][row] = kv4.x; Ks[0][col+1][row] = kv4.y;
        Ks[0][col+2][row] = kv4.z; Ks[0][col+3][row] = kv4.w;
    }
    __syncthreads();
    float acc[4][4] = {};
#pragma unroll
    for (int t = 0; t < 4; t++) {
        int cur = t & 1, nxt = cur ^ 1;
        float4 qv4, kv4;
        bool more = (t + 1 < 4);
        if (more) {
            int k0 = (t + 1) << 4;
            qv4 = *reinterpret_cast<const float4*>(Q + (size_t)(m0 + row) * DH_ + k0 + col);
            kv4 = *reinterpret_cast<const float4*>(Km + (size_t)(n0 + row) * DH_ + k0 + col);
        }
#pragma unroll
        for (int kk = 0; kk < 16; kk++) {
            float4 a4 = *reinterpret_cast<const float4*>(&Qs[cur][kk][ty*4]);
            float4 b4 = *reinterpret_cast<const float4*>(&Ks[cur][kk][tx*4]);
            float ar[4] = {a4.x, a4.y, a4.z, a4.w};
            float br[4] = {b4.x, b4.y, b4.z, b4.w};
#pragma unroll
            for (int i = 0; i < 4; i++)
#pragma unroll
                for (int j = 0; j < 4; j++)
                    acc[i][j] = fmaf(ar[i], br[j], acc[i][j]);
        }
        if (more) {
            Qs[nxt][col+0][row] = qv4.x; Qs[nxt][col+1][row] = qv4.y;
            Qs[nxt][col+2][row] = qv4.z; Qs[nxt][col+3][row] = qv4.w;
            Ks[nxt][col+0][row] = kv4.x; Ks[nxt][col+1][row] = kv4.y;
            Ks[nxt][col+2][row] = kv4.z; Ks[nxt][col+3][row] = kv4.w;
        }
        __syncthreads();
    }
#pragma unroll
    for (int i = 0; i < 4; i++) {
        int q = m0 + ty*4 + i;
        int qv = q / GW_, qh = q - qv * GW_;
        const float* pbq = g_pb + ((size_t)h * S_ + q) * 64;
        float pb0 = pbq[0];
        unsigned* srow = g_skey + ((size_t)h * S_ + q) * S_;
        unsigned kbuf[4];
#pragma unroll
        for (int j = 0; j < 4; j++) {
            int kq = n0 + tx*4 + j;
            int kv = kq / GW_, kh = kq - kv * GW_;
            int dv = kv - qv, dh = kh - qh;
            int ad = (dv < 0 ? -dv : dv) + (dh < 0 ? -dh : dh);
            float pbv = (ad <= 3) ? pbq[(dv + 3) * 7 + (dh + 3)] : pb0;
            float s = (acc[i][j] + pbv) * SCALE_;
            unsigned b = __float_as_uint(s);
            kbuf[j] = (b & 0x80000000u) ? ~b : (b | 0x80000000u);
        }
        *reinterpret_cast<uint4*>(srow + n0 + tx*4) = make_uint4(kbuf[0], kbuf[1], kbuf[2], kbuf[3]);
    }
}

// ---------------- attn_row: register keys + warp-aggregated hist + parallel select ----------------
__global__ void __launch_bounds__(256) attn_row_kernel() {
    int bx = blockIdx.x;                 // h*S + q
    int h = bx / S_, q = bx - h * S_;
    const unsigned* srow = g_skey + (size_t)bx * S_;
    __shared__ unsigned hist[256];
    __shared__ unsigned sufw[8];
    __shared__ int   sidx[256];
    __shared__ float sval[256];
    __shared__ float pvred[4][DH_];
    __shared__ unsigned smaxw[8];
    __shared__ float ssum[8];
    __shared__ int sh_b, sh_k, sh_k2, sh_cnt;
    __shared__ float sh_inv;
    __shared__ unsigned sh_maxu;
    int tid = threadIdx.x;
    int wid = tid >> 5, lane = tid & 31;

    // keys in registers: key[j] = srow[tid + j*256]; S = 6*256 + 64
    unsigned key[7];
    int nkk = (tid < 64) ? 7 : 6;
#pragma unroll
    for (int j = 0; j < 6; j++) key[j] = srow[tid + j*256];
    key[6] = (tid < 64) ? srow[tid + 1536] : 0u;

    // block max key
    unsigned mxu = 0u;
#pragma unroll
    for (int j = 0; j < 7; j++) mxu = max(mxu, key[j]);
    for (int o = 16; o; o >>= 1) mxu = max(mxu, __shfl_xor_sync(0xffffffffu, mxu, o));
    if (lane == 0) smaxw[wid] = mxu;
    if (tid == 0) { sh_k = TOPK_; sh_cnt = 0; }
    __syncthreads();
    if (tid == 0) {
        unsigned m = smaxw[0];
#pragma unroll
        for (int w = 1; w < 8; w++) m = max(m, smaxw[w]);
        sh_maxu = m;
    }

    // 4-pass radix select, warp-aggregated histogram, parallel suffix select
    unsigned pref = 0u;
    for (int shift = 24; shift >= 0; shift -= 8) {
        hist[tid] = 0u;
        __syncthreads();
        unsigned maskhi = (shift == 24) ? 0u : (0xFFFFFFFFu << (shift + 8));
        for (int j = 0; j < nkk; j++) {
            unsigned u = key[j];
            if ((u & maskhi) == pref) {
                unsigned b = (u >> shift) & 255u;
                unsigned act = __activemask();
                unsigned mmask = __match_any_sync(act, b);
                int leader = __ffs(mmask) - 1;
                if (lane == leader) atomicAdd(&hist[b], (unsigned)__popc(mmask));
            }
        }
        __syncthreads();
        // parallel suffix sums over 256 bins
        unsigned c = hist[tid];
        unsigned s = c;
#pragma unroll
        for (int o = 1; o < 32; o <<= 1) {
            unsigned t = __shfl_down_sync(0xffffffffu, s, o);
            if (lane + o < 32) s += t;
        }
        if (lane == 0) sufw[wid] = s;
        __syncthreads();
        unsigned add = 0;
        for (int w = wid + 1; w < 8; w++) add += sufw[w];
        unsigned suf_incl = s + add;
        unsigned suf_excl = suf_incl - c;
        unsigned kkr = (unsigned)sh_k;
        if (suf_incl >= kkr && suf_excl < kkr) { sh_b = tid; sh_k2 = (int)(kkr - suf_excl); }
        __syncthreads();
        pref |= ((unsigned)sh_b) << shift;
        if (tid == 0) sh_k = sh_k2;
        __syncthreads();
    }
    unsigned thr = pref;
    unsigned mu = sh_maxu;
    float mxv = (mu & 0x80000000u) ? __uint_as_float(mu ^ 0x80000000u) : __uint_as_float(~mu);

    // gather survivors + exp (score recovered from key)
    for (int j = 0; j < nkk; j++) {
        unsigned u = key[j];
        if (u >= thr) {
            int p = atomicAdd(&sh_cnt, 1);
            if (p < 256) {
                float v = (u & 0x80000000u) ? __uint_as_float(u ^ 0x80000000u)
                                            : __uint_as_float(~u);
                sidx[p] = tid + j*256;
                sval[p] = expf(v - mxv);
            }
        }
    }
    __syncthreads();
    int cnt = min(sh_cnt, 256);

    // parallel sum of exp weights
    {
        float s = 0.f;
        for (int i = tid; i < cnt; i += 256) s += sval[i];
        for (int o = 16; o; o >>= 1) s += __shfl_xor_sync(0xffffffffu, s, o);
        if (lane == 0) ssum[wid] = s;
        __syncthreads();
        if (tid == 0) {
            float t = ssum[0];
#pragma unroll
            for (int w = 1; w < 8; w++) t += ssum[w];
            sh_inv = 1.f / t;
        }
        __syncthreads();
    }

    // sparse P.V with 4-way split over survivors
    {
        int g = tid >> 6, d = tid & 63;
        const float* V = g_v + (size_t)h * S_ * DH_;
        float acc = 0.f;
        for (int i = g; i < cnt; i += 4) acc = fmaf(sval[i], V[sidx[i] * DH_ + d], acc);
        pvred[g][d] = acc;
        __syncthreads();
        if (tid < DH_) {
            float r = pvred[0][tid] + pvred[1][tid] + pvred[2][tid] + pvred[3][tid];
            g_att[q * INNER_ + h * DH_ + tid] = r * sh_inv;
        }
    }
}

// ---------------- host launcher ----------------
extern "C" void kernel_launch(void* const* d_in, const int* in_sizes, int n_in,
                              void* d_out, int out_size) {
    (void)in_sizes; (void)n_in; (void)out_size;
    const float* x    = (const float*)d_in[0];
    const float* Wqkv = (const float*)d_in[1];
    const float* Wo   = (const float*)d_in[2];
    const float* ln1g = (const float*)d_in[3];
    const float* ln1b = (const float*)d_in[4];
    const float* ln2g = (const float*)d_in[5];
    const float* ln2b = (const float*)d_in[6];
    const float* relb = (const float*)d_in[7];
    const float* w1   = (const float*)d_in[8];
    const float* b1   = (const float*)d_in[9];
    const float* w2   = (const float*)d_in[10];
    const float* b2   = (const float*)d_in[11];

    init_h_kernel<<<(S_*DIM_ + 255) / 256, 256>>>(x);
    rbT_kernel<<<16, 256>>>(relb);

    for (int l = 0; l < NL_; l++) {
        ln_kernel<<<S_, 128>>>(ln1g + l*DIM_, ln1b + l*DIM_);
        gemm64db<0><<<dim3(18, 25), 256>>>(Wqkv + (size_t)l*DIM_*3*INNER_, nullptr, 3*INNER_, DIM_);
        pb_gemm<<<dim3(1, (NH_*S_)/64), 256>>>();
        scores64db<<<dim3(25, 25, NH_), 256>>>();
        attn_row_kernel<<<NH_*S_, 256>>>();
        gemm64db<1><<<dim3(6, 25), 256>>>(Wo + (size_t)l*INNER_*DIM_, nullptr, DIM_, INNER_);
        ln_kernel<<<S_, 128>>>(ln2g + l*DIM_, ln2b + l*DIM_);
        gemm64db<2><<<dim3(24, 25), 256>>>(w1 + (size_t)l*DIM_*HID_, b1 + l*HID_, HID_, DIM_);
        gemm64db<3><<<dim3(6, 25), 256>>>(w2 + (size_t)l*HID_*DIM_, b2 + l*DIM_, DIM_, HID_);
    }

    write_out_kernel<<<(S_*DIM_ + 255) / 256, 256>>>((float*)d_out);
}

// round 9
// speedup vs baseline: 2.0103x; 1.0218x over previous
#include <cuda_runtime.h>
#include <float.h>

#define S_    1600
#define DIM_  384
#define NH_   6
#define DH_   64
#define INNER_ 384
#define HID_  1536
#define NL_   6
#define GW_   40
#define TOPK_ 32
#define SCALE_ 0.05103103630798288f   // 384^-0.5

// ---------------- device scratch ----------------
__device__ float g_h[S_*DIM_];
__device__ float g_n[S_*DIM_];
__device__ float g_q[NH_*S_*DH_];
__device__ float g_k[NH_*S_*DH_];
__device__ float g_v[NH_*S_*DH_];
__device__ float g_pb[NH_*S_*64];
__device__ float g_rbT[64*64];
__device__ unsigned g_skey[(long long)NH_*S_*S_];
__device__ float g_att[S_*INNER_];
__device__ float g_ff1[S_*HID_];

// ---------------- tf32 helpers ----------------
__device__ __forceinline__ unsigned f2tf32(float x) {
    unsigned r;
    asm("cvt.rna.tf32.f32 %0, %1;" : "=r"(r) : "f"(x));
    return r;
}
__device__ __forceinline__ void mma_tf32(float* c, const unsigned* a, const unsigned* b) {
    asm volatile(
        "mma.sync.aligned.m16n8k8.row.col.f32.tf32.tf32.f32 "
        "{%0,%1,%2,%3}, {%4,%5,%6,%7}, {%8,%9}, {%0,%1,%2,%3};"
        : "+f"(c[0]), "+f"(c[1]), "+f"(c[2]), "+f"(c[3])
        : "r"(a[0]), "r"(a[1]), "r"(a[2]), "r"(a[3]), "r"(b[0]), "r"(b[1]));
}

// ---------------- trivial kernels ----------------
__global__ void init_h_kernel(const float* __restrict__ x) {
    int i = blockIdx.x * blockDim.x + threadIdx.x;
    if (i < S_*DIM_) g_h[i] = x[i];
}
__global__ void write_out_kernel(float* __restrict__ out) {
    int i = blockIdx.x * blockDim.x + threadIdx.x;
    if (i < S_*DIM_) out[i] = g_h[i];
}
__global__ void rbT_kernel(const float* __restrict__ rb) {
    int i = blockIdx.x * blockDim.x + threadIdx.x;
    if (i < 64*64) {
        int d = i >> 6, m = i & 63;
        g_rbT[d*64 + m] = (m < 49) ? rb[m*64 + d] : 0.f;
    }
}

// ---------------- LayerNorm ----------------
__global__ void ln_kernel(const float* __restrict__ gamma, const float* __restrict__ beta) {
    int row = blockIdx.x;
    const float* x = g_h + row * DIM_;
    float s = 0.f, s2 = 0.f;
    for (int i = threadIdx.x; i < DIM_; i += blockDim.x) { float v = x[i]; s += v; s2 += v*v; }
    for (int o = 16; o; o >>= 1) {
        s  += __shfl_xor_sync(0xffffffffu, s,  o);
        s2 += __shfl_xor_sync(0xffffffffu, s2, o);
    }
    __shared__ float rs[4], rs2[4];
    int w = threadIdx.x >> 5;
    if ((threadIdx.x & 31) == 0) { rs[w] = s; rs2[w] = s2; }
    __syncthreads();
    s  = rs[0]  + rs[1]  + rs[2]  + rs[3];
    s2 = rs2[0] + rs2[1] + rs2[2] + rs2[3];
    float mean = s * (1.f / DIM_);
    float var  = s2 * (1.f / DIM_) - mean * mean;
    float inv  = rsqrtf(var + 1e-5f);
    for (int i = threadIdx.x; i < DIM_; i += blockDim.x)
        g_n[row*DIM_ + i] = (x[i] - mean) * inv * gamma[i] + beta[i];
}

// ========== double-buffered 64x64x16 SGEMM, 4x4 register tiles ==========
template<int MODE>
__global__ void __launch_bounds__(256) gemm64db(const float* __restrict__ B,
                                                const float* __restrict__ bias,
                                                int N, int K) {
    const float* A = (MODE == 0 || MODE == 2) ? g_n : (MODE == 1 ? g_att : g_ff1);
    __shared__ __align__(16) float As[2][16][68];
    __shared__ __align__(16) float Bs[2][16][68];
    int tid = threadIdx.x;
    int tx = tid & 15, ty = tid >> 4;
    int m0 = blockIdx.y * 64, n0 = blockIdx.x * 64;
    int arow = tid >> 2, acol = (tid & 3) * 4;
    int brow = tid >> 4, bcol = (tid & 15) * 4;
    const int nk = K >> 4;
    {
        float4 av = *reinterpret_cast<const float4*>(A + (size_t)(m0 + arow) * K + acol);
        As[0][acol+0][arow] = av.x; As[0][acol+1][arow] = av.y;
        As[0][acol+2][arow] = av.z; As[0][acol+3][arow] = av.w;
        float4 bv = *reinterpret_cast<const float4*>(B + (size_t)brow * N + n0 + bcol);
        *reinterpret_cast<float4*>(&Bs[0][brow][bcol]) = bv;
    }
    __syncthreads();
    float acc[4][4] = {};
    for (int t = 0; t < nk; t++) {
        int cur = t & 1, nxt = cur ^ 1;
        float4 av, bv;
        bool more = (t + 1 < nk);
        if (more) {
            int k0 = (t + 1) << 4;
            av = *reinterpret_cast<const float4*>(A + (size_t)(m0 + arow) * K + k0 + acol);
            bv = *reinterpret_cast<const float4*>(B + (size_t)(k0 + brow) * N + n0 + bcol);
        }
#pragma unroll
        for (int kk = 0; kk < 16; kk++) {
            float4 a4 = *reinterpret_cast<const float4*>(&As[cur][kk][ty*4]);
            float4 b4 = *reinterpret_cast<const float4*>(&Bs[cur][kk][tx*4]);
            float ar[4] = {a4.x, a4.y, a4.z, a4.w};
            float br[4] = {b4.x, b4.y, b4.z, b4.w};
#pragma unroll
            for (int i = 0; i < 4; i++)
#pragma unroll
                for (int j = 0; j < 4; j++)
                    acc[i][j] = fmaf(ar[i], br[j], acc[i][j]);
        }
        if (more) {
            As[nxt][acol+0][arow] = av.x; As[nxt][acol+1][arow] = av.y;
            As[nxt][acol+2][arow] = av.z; As[nxt][acol+3][arow] = av.w;
            *reinterpret_cast<float4*>(&Bs[nxt][brow][bcol]) = bv;
        }
        __syncthreads();
    }
#pragma unroll
    for (int i = 0; i < 4; i++) {
        int m = m0 + ty*4 + i;
#pragma unroll
        for (int j = 0; j < 4; j++) {
            int n = n0 + tx*4 + j;
            float v = acc[i][j];
            if (MODE == 0) {
                int idx = n / 3, r = n - idx * 3;
                int hh = idx >> 6, d = idx & 63;
                float* dst = (r == 0) ? g_q : (r == 1) ? g_k : g_v;
                dst[(hh * S_ + m) * DH_ + d] = v;
            } else if (MODE == 1) {
                g_h[m * DIM_ + n] += v;
            } else if (MODE == 2) {
                float t2 = v + bias[n];
                g_ff1[m * HID_ + n] = t2 > 0.f ? t2 : 0.2f * t2;
            } else {
                g_h[m * DIM_ + n] += v + bias[n];
            }
        }
    }
}

// ---------------- pb GEMM: g_pb[9600x64] = g_q @ g_rbT ----------------
__global__ void __launch_bounds__(256) pb_gemm() {
    const float* A = g_q;
    const float* B = g_rbT;
    __shared__ __align__(16) float As[16][68];
    __shared__ __align__(16) float Bs[16][68];
    int tid = threadIdx.x;
    int tx = tid & 15, ty = tid >> 4;
    int m0 = blockIdx.y * 64;
    int arow = tid >> 2, acol = (tid & 3) * 4;
    int brow = tid >> 4, bcol = (tid & 15) * 4;
    float acc[4][4] = {};
    for (int k0 = 0; k0 < 64; k0 += 16) {
        float4 av = *reinterpret_cast<const float4*>(A + (size_t)(m0 + arow) * 64 + k0 + acol);
        As[acol+0][arow] = av.x; As[acol+1][arow] = av.y;
        As[acol+2][arow] = av.z; As[acol+3][arow] = av.w;
        float4 bv = *reinterpret_cast<const float4*>(B + (size_t)(k0 + brow) * 64 + bcol);
        *reinterpret_cast<float4*>(&Bs[brow][bcol]) = bv;
        __syncthreads();
#pragma unroll
        for (int kk = 0; kk < 16; kk++) {
            float4 a4 = *reinterpret_cast<const float4*>(&As[kk][ty*4]);
            float4 b4 = *reinterpret_cast<const float4*>(&Bs[kk][tx*4]);
            float ar[4] = {a4.x, a4.y, a4.z, a4.w};
            float br[4] = {b4.x, b4.y, b4.z, b4.w};
#pragma unroll
            for (int i = 0; i < 4; i++)
#pragma unroll
                for (int j = 0; j < 4; j++)
                    acc[i][j] = fmaf(ar[i], br[j], acc[i][j]);
        }
        __syncthreads();
    }
#pragma unroll
    for (int i = 0; i < 4; i++)
#pragma unroll
        for (int j = 0; j < 4; j++)
            g_pb[(m0 + ty*4 + i) * 64 + tx*4 + j] = acc[i][j];
}

// ---------------- scores via tf32 tensor-core MMA (split for fp32 accuracy) ----------------
// D = Q @ K^T, Q/K fp32. Split x = hi + lo (hi = tf32(x), lo = tf32(x - hi));
// D ≈ Qhi·Khi + Qhi·Klo + Qlo·Khi  (error ~2^-22 relative).
// Block 64x64 output, 8 warps; warp tile 16x32 (4 n-tiles of m16n8k8).
__global__ void __launch_bounds__(256) scores_mma() {
    int h = blockIdx.z;
    const float* Q  = g_q + (size_t)h * S_ * DH_;
    const float* Km = g_k + (size_t)h * S_ * DH_;
    __shared__ __align__(16) float Qs[64][68];
    __shared__ __align__(16) float Ks[64][68];
    int tid = threadIdx.x;
    int m0 = blockIdx.y * 64, n0 = blockIdx.x * 64;

    // load Q,K tiles (each thread: 4 float4 per array)
#pragma unroll
    for (int i = 0; i < 4; i++) {
        int e = tid + i * 256;
        int row = e >> 4, c = (e & 15) * 4;
        *reinterpret_cast<float4*>(&Qs[row][c]) =
            *reinterpret_cast<const float4*>(Q + (size_t)(m0 + row) * DH_ + c);
        *reinterpret_cast<float4*>(&Ks[row][c]) =
            *reinterpret_cast<const float4*>(Km + (size_t)(n0 + row) * DH_ + c);
    }
    __syncthreads();

    int wid = tid >> 5, lane = tid & 31;
    int wy = wid >> 1, wx = wid & 1;
    int gr = lane >> 2, tg = lane & 3;

    float acc[4][4] = {};
#pragma unroll
    for (int k0 = 0; k0 < 64; k0 += 8) {
        // A fragment (m16k8): rows wy*16+gr, +8 ; cols k0+tg, +4
        int ar = wy*16 + gr;
        float a[4];
        a[0] = Qs[ar    ][k0 + tg];
        a[1] = Qs[ar + 8][k0 + tg];
        a[2] = Qs[ar    ][k0 + tg + 4];
        a[3] = Qs[ar + 8][k0 + tg + 4];
        unsigned ah[4], al[4];
#pragma unroll
        for (int i = 0; i < 4; i++) {
            ah[i] = f2tf32(a[i]);
            al[i] = f2tf32(a[i] - __uint_as_float(ah[i]));
        }
#pragma unroll
        for (int t = 0; t < 4; t++) {
            // B fragment (k8n8, col-major == K row-major [n][k]): n = tile + gr, k = k0+tg, +4
            int bn = wx*32 + t*8 + gr;
            float b0 = Ks[bn][k0 + tg];
            float b1 = Ks[bn][k0 + tg + 4];
            unsigned bh[2], bl[2];
            bh[0] = f2tf32(b0); bl[0] = f2tf32(b0 - __uint_as_float(bh[0]));
            bh[1] = f2tf32(b1); bl[1] = f2tf32(b1 - __uint_as_float(bh[1]));
            mma_tf32(acc[t], ah, bh);
            mma_tf32(acc[t], ah, bl);
            mma_tf32(acc[t], al, bh);
        }
    }

    // epilogue: bias gather + monotone key, write uint2 (adjacent cols)
#pragma unroll
    for (int rr = 0; rr < 2; rr++) {
        int q = m0 + wy*16 + gr + rr*8;
        int qv = q / GW_, qh = q - qv * GW_;
        const float* pbq = g_pb + ((size_t)h * S_ + q) * 64;
        float pb0 = pbq[0];
        unsigned* srow = g_skey + ((size_t)h * S_ + q) * S_;
#pragma unroll
        for (int t = 0; t < 4; t++) {
            int kq0 = n0 + wx*32 + t*8 + tg*2;
            unsigned kb[2];
#pragma unroll
            for (int cc = 0; cc < 2; cc++) {
                int kq = kq0 + cc;
                int kv = kq / GW_, kh = kq - kv * GW_;
                int dv = kv - qv, dh = kh - qh;
                int ad = (dv < 0 ? -dv : dv) + (dh < 0 ? -dh : dh);
                float pbv = (ad <= 3) ? pbq[(dv + 3) * 7 + (dh + 3)] : pb0;
                float sc = (acc[t][rr*2 + cc] + pbv) * SCALE_;
                unsigned bts = __float_as_uint(sc);
                kb[cc] = (bts & 0x80000000u) ? ~bts : (bts | 0x80000000u);
            }
            *reinterpret_cast<uint2*>(srow + kq0) = make_uint2(kb[0], kb[1]);
        }
    }
}

// ---------------- attn_row: register keys + warp-aggregated hist + parallel select ----------------
__global__ void __launch_bounds__(256) attn_row_kernel() {
    int bx = blockIdx.x;                 // h*S + q
    int h = bx / S_, q = bx - h * S_;
    const unsigned* srow = g_skey + (size_t)bx * S_;
    __shared__ unsigned hist[256];
    __shared__ unsigned sufw[8];
    __shared__ int   sidx[256];
    __shared__ float sval[256];
    __shared__ float pvred[4][DH_];
    __shared__ unsigned smaxw[8];
    __shared__ float ssum[8];
    __shared__ int sh_b, sh_k, sh_k2, sh_cnt;
    __shared__ float sh_inv;
    __shared__ unsigned sh_maxu;
    int tid = threadIdx.x;
    int wid = tid >> 5, lane = tid & 31;

    unsigned key[7];
    int nkk = (tid < 64) ? 7 : 6;
#pragma unroll
    for (int j = 0; j < 6; j++) key[j] = srow[tid + j*256];
    key[6] = (tid < 64) ? srow[tid + 1536] : 0u;

    unsigned mxu = 0u;
#pragma unroll
    for (int j = 0; j < 7; j++) mxu = max(mxu, key[j]);
    for (int o = 16; o; o >>= 1) mxu = max(mxu, __shfl_xor_sync(0xffffffffu, mxu, o));
    if (lane == 0) smaxw[wid] = mxu;
    if (tid == 0) { sh_k = TOPK_; sh_cnt = 0; }
    __syncthreads();
    if (tid == 0) {
        unsigned m = smaxw[0];
#pragma unroll
        for (int w = 1; w < 8; w++) m = max(m, smaxw[w]);
        sh_maxu = m;
    }

    unsigned pref = 0u;
    for (int shift = 24; shift >= 0; shift -= 8) {
        hist[tid] = 0u;
        __syncthreads();
        unsigned maskhi = (shift == 24) ? 0u : (0xFFFFFFFFu << (shift + 8));
        for (int j = 0; j < nkk; j++) {
            unsigned u = key[j];
            if ((u & maskhi) == pref) {
                unsigned b = (u >> shift) & 255u;
                unsigned act = __activemask();
                unsigned mmask = __match_any_sync(act, b);
                int leader = __ffs(mmask) - 1;
                if (lane == leader) atomicAdd(&hist[b], (unsigned)__popc(mmask));
            }
        }
        __syncthreads();
        unsigned c = hist[tid];
        unsigned s = c;
#pragma unroll
        for (int o = 1; o < 32; o <<= 1) {
            unsigned t = __shfl_down_sync(0xffffffffu, s, o);
            if (lane + o < 32) s += t;
        }
        if (lane == 0) sufw[wid] = s;
        __syncthreads();
        unsigned add = 0;
        for (int w = wid + 1; w < 8; w++) add += sufw[w];
        unsigned suf_incl = s + add;
        unsigned suf_excl = suf_incl - c;
        unsigned kkr = (unsigned)sh_k;
        if (suf_incl >= kkr && suf_excl < kkr) { sh_b = tid; sh_k2 = (int)(kkr - suf_excl); }
        __syncthreads();
        pref |= ((unsigned)sh_b) << shift;
        if (tid == 0) sh_k = sh_k2;
        __syncthreads();
    }
    unsigned thr = pref;
    unsigned mu = sh_maxu;
    float mxv = (mu & 0x80000000u) ? __uint_as_float(mu ^ 0x80000000u) : __uint_as_float(~mu);

    for (int j = 0; j < nkk; j++) {
        unsigned u = key[j];
        if (u >= thr) {
            int p = atomicAdd(&sh_cnt, 1);
            if (p < 256) {
                float v = (u & 0x80000000u) ? __uint_as_float(u ^ 0x80000000u)
                                            : __uint_as_float(~u);
                sidx[p] = tid + j*256;
                sval[p] = expf(v - mxv);
            }
        }
    }
    __syncthreads();
    int cnt = min(sh_cnt, 256);

    {
        float s = 0.f;
        for (int i = tid; i < cnt; i += 256) s += sval[i];
        for (int o = 16; o; o >>= 1) s += __shfl_xor_sync(0xffffffffu, s, o);
        if (lane == 0) ssum[wid] = s;
        __syncthreads();
        if (tid == 0) {
            float t = ssum[0];
#pragma unroll
            for (int w = 1; w < 8; w++) t += ssum[w];
            sh_inv = 1.f / t;
        }
        __syncthreads();
    }

    {
        int g = tid >> 6, d = tid & 63;
        const float* V = g_v + (size_t)h * S_ * DH_;
        float acc = 0.f;
        for (int i = g; i < cnt; i += 4) acc = fmaf(sval[i], V[sidx[i] * DH_ + d], acc);
        pvred[g][d] = acc;
        __syncthreads();
        if (tid < DH_) {
            float r = pvred[0][tid] + pvred[1][tid] + pvred[2][tid] + pvred[3][tid];
            g_att[q * INNER_ + h * DH_ + tid] = r * sh_inv;
        }
    }
}

// ---------------- host launcher ----------------
extern "C" void kernel_launch(void* const* d_in, const int* in_sizes, int n_in,
                              void* d_out, int out_size) {
    (void)in_sizes; (void)n_in; (void)out_size;
    const float* x    = (const float*)d_in[0];
    const float* Wqkv = (const float*)d_in[1];
    const float* Wo   = (const float*)d_in[2];
    const float* ln1g = (const float*)d_in[3];
    const float* ln1b = (const float*)d_in[4];
    const float* ln2g = (const float*)d_in[5];
    const float* ln2b = (const float*)d_in[6];
    const float* relb = (const float*)d_in[7];
    const float* w1   = (const float*)d_in[8];
    const float* b1   = (const float*)d_in[9];
    const float* w2   = (const float*)d_in[10];
    const float* b2   = (const float*)d_in[11];

    init_h_kernel<<<(S_*DIM_ + 255) / 256, 256>>>(x);
    rbT_kernel<<<16, 256>>>(relb);

    for (int l = 0; l < NL_; l++) {
        ln_kernel<<<S_, 128>>>(ln1g + l*DIM_, ln1b + l*DIM_);
        gemm64db<0><<<dim3(18, 25), 256>>>(Wqkv + (size_t)l*DIM_*3*INNER_, nullptr, 3*INNER_, DIM_);
        pb_gemm<<<dim3(1, (NH_*S_)/64), 256>>>();
        scores_mma<<<dim3(25, 25, NH_), 256>>>();
        attn_row_kernel<<<NH_*S_, 256>>>();
        gemm64db<1><<<dim3(6, 25), 256>>>(Wo + (size_t)l*INNER_*DIM_, nullptr, DIM_, INNER_);
        ln_kernel<<<S_, 128>>>(ln2g + l*DIM_, ln2b + l*DIM_);
        gemm64db<2><<<dim3(24, 25), 256>>>(w1 + (size_t)l*DIM_*HID_, b1 + l*HID_, HID_, DIM_);
        gemm64db<3><<<dim3(6, 25), 256>>>(w2 + (size_t)l*HID_*DIM_, b2 + l*DIM_, DIM_, HID_);
    }

    write_out_kernel<<<(S_*DIM_ + 255) / 256, 256>>>((float*)d_out);
}